// round 12
// baseline (speedup 1.0000x reference)
#include <cuda_runtime.h>
#include <cuda_bf16.h>
#include <cstdint>

// ---------------------------------------------------------------------------
// Non-local attention block, B=8, C=512, N=1024 (H=W=32), fp32 in/out.
// R11: 4-stage cp.async pipeline (BK=16, 48B-padded rows, wait_group 2,
//      2 CTAs/SM kept) — attacks the bandwidth-delay starvation of the
//      2-stage loop. Same 64x32 warp tiles (best LDSM/MMA ratio).
// ---------------------------------------------------------------------------

namespace {
constexpr int Cd = 512, Nd = 1024, Bd = 8;
constexpr int BK     = 16;                 // k per pipeline stage
constexpr int ROWB   = 48;                 // padded smem row (16 bf16 = 32B data)
constexpr int TILE_B = 128 * ROWB;         // 6144 B per operand-half tile
constexpr int BUF_B  = 4 * TILE_B;         // Ahi,Alo,Bhi,Blo = 24576 per stage
constexpr int STAGES = 4;
constexpr int SM_TOTAL = STAGES * BUF_B;   // 98304
}

// ---- device scratch --------------------------------------------------------
__device__ __nv_bfloat16 g_XT_hi[Bd * Nd * Cd];    // [b][n][c]
__device__ __nv_bfloat16 g_XT_lo[Bd * Nd * Cd];
__device__ __nv_bfloat16 g_WT_hi[2 * Cd * Cd];     // rows 0-511 WphiT, 512-1023 WthetaT
__device__ __nv_bfloat16 g_WT_lo[2 * Cd * Cd];
__device__ __nv_bfloat16 g_Wb_hi[Cd * Cd];         // Wbeta row-major [c][k]
__device__ __nv_bfloat16 g_Wb_lo[Cd * Cd];
__device__ float         g_bias_b[Cd];
__device__ float         g_v[Cd];                  // Wtheta^T bphi
__device__ float         g_u[Bd * Nd];             // v^T X_b
__device__ float         g_rmax[Bd * Nd];          // row max of S_eff
__device__ float         g_rinv[Bd * Nd];          // 1 / row sum exp
__device__ __nv_bfloat16 g_M_hi[Cd * Cd];          // [c][k]
__device__ __nv_bfloat16 g_M_lo[Cd * Cd];
__device__ __nv_bfloat16 g_TT_hi[Bd * Nd * Cd];    // [b][m][c]
__device__ __nv_bfloat16 g_TT_lo[Bd * Nd * Cd];
__device__ __nv_bfloat16 g_beta_hi[Bd * Cd * Nd];  // [b][c][n]
__device__ __nv_bfloat16 g_beta_lo[Bd * Cd * Nd];
__device__ float         g_S[Bd * Nd * Nd];        // [b][n][m]
__device__ __nv_bfloat16 g_AT_hi[Bd * Nd * Nd];    // [b][m][n]
__device__ __nv_bfloat16 g_AT_lo[Bd * Nd * Nd];

// ---- helpers ---------------------------------------------------------------
__device__ __forceinline__ uint32_t smem_u32(const void* p) {
    uint32_t a;
    asm("{ .reg .u64 t; cvta.to.shared.u64 t, %1; cvt.u32.u64 %0, t; }"
        : "=r"(a) : "l"(p));
    return a;
}
__device__ __forceinline__ void cp16(uint32_t dst, const void* src) {
    asm volatile("cp.async.cg.shared.global [%0], [%1], 16;"
                 :: "r"(dst), "l"(__cvta_generic_to_global(src)) : "memory");
}
__device__ __forceinline__ void cp_commit() {
    asm volatile("cp.async.commit_group;" ::: "memory");
}
__device__ __forceinline__ void cp_wait2() {
    asm volatile("cp.async.wait_group 2;" ::: "memory");
}
__device__ __forceinline__ void ldm_x4(uint32_t (&r)[4], uint32_t addr) {
    asm volatile("ldmatrix.sync.aligned.m8n8.x4.shared.b16 {%0,%1,%2,%3}, [%4];"
        : "=r"(r[0]), "=r"(r[1]), "=r"(r[2]), "=r"(r[3]) : "r"(addr));
}
__device__ __forceinline__ void mma_bf16(float (&d)[4], const uint32_t (&a)[4],
                                         const uint32_t b0, const uint32_t b1) {
    asm volatile(
        "mma.sync.aligned.m16n8k16.row.col.f32.bf16.bf16.f32 "
        "{%0,%1,%2,%3},{%4,%5,%6,%7},{%8,%9},{%0,%1,%2,%3};"
        : "+f"(d[0]), "+f"(d[1]), "+f"(d[2]), "+f"(d[3])
        : "r"(a[0]), "r"(a[1]), "r"(a[2]), "r"(a[3]), "r"(b0), "r"(b1));
}
__device__ __forceinline__ void split_bf16(float v, __nv_bfloat16& h, __nv_bfloat16& l) {
    h = __float2bfloat16(v);
    l = __float2bfloat16(v - __bfloat162float(h));
}

// ---------------------------------------------------------------------------
// v[i] = sum_q Wt[q][i] * bphi[q]  — atomic-free: 16 blocks x (32 i, 8 q-warps)
// ---------------------------------------------------------------------------
__global__ __launch_bounds__(256)
void k_v(const float* __restrict__ Wt, const float* __restrict__ bphi)
{
    __shared__ float part[8][32];
    const int i  = blockIdx.x * 32 + (threadIdx.x & 31);
    const int qs = threadIdx.x >> 5;
    float s = 0.f;
    #pragma unroll 8
    for (int r = 0; r < 64; r++) {
        const int q = qs * 64 + r;
        s += Wt[(size_t)q * Cd + i] * bphi[q];
    }
    part[qs][threadIdx.x & 31] = s;
    __syncthreads();
    if (qs == 0) {
        float t = part[0][threadIdx.x];
        #pragma unroll
        for (int w = 1; w < 8; w++) t += part[w][threadIdx.x];
        g_v[i] = t;
    }
}

// ---------------------------------------------------------------------------
// u[b][m] += sum_{k in chunk} v[k] * X[b][k][m]   (g_u zeroed by k_prep_wb)
// ---------------------------------------------------------------------------
__global__ __launch_bounds__(256)
void k_u(const float* __restrict__ X)
{
    __shared__ float vs[64];
    const int kc = blockIdx.y;
    if (threadIdx.x < 64) vs[threadIdx.x] = g_v[kc * 64 + threadIdx.x];
    __syncthreads();
    const int g = blockIdx.x * 256 + threadIdx.x;
    const int b = g >> 10, m = g & 1023;
    const float* xp = X + ((size_t)b * Cd + kc * 64) * Nd + m;
    float s = 0.f;
    #pragma unroll 8
    for (int k = 0; k < 64; k++) s += vs[k] * xp[(size_t)k * Nd];
    atomicAdd(&g_u[g], s);
}

// ---------------------------------------------------------------------------
// prep WT: transpose + split Wphi, Wtheta
// ---------------------------------------------------------------------------
__global__ __launch_bounds__(256)
void k_prep_wt(const float* __restrict__ Wp, const float* __restrict__ Wt)
{
    __shared__ float t[32][33];
    const float* W = (blockIdx.z == 0) ? Wp : Wt;
    const int r0 = blockIdx.x * 32, q0 = blockIdx.y * 32;
    const int tx = threadIdx.x, ty = threadIdx.y;
    #pragma unroll
    for (int r = 0; r < 4; r++)
        t[ty + 8 * r][tx] = W[(size_t)(q0 + ty + 8 * r) * Cd + r0 + tx];
    __syncthreads();
    #pragma unroll
    for (int r = 0; r < 4; r++) {
        float v = t[tx][ty + 8 * r];
        size_t o = ((size_t)blockIdx.z * Cd + r0 + ty + 8 * r) * Cd + q0 + tx;
        split_bf16(v, g_WT_hi[o], g_WT_lo[o]);
    }
}

// ---------------------------------------------------------------------------
// prep Wb: row-major split + beta bias copy + zero g_u
// ---------------------------------------------------------------------------
__global__ __launch_bounds__(256)
void k_prep_wb(const float* __restrict__ Wb, const float* __restrict__ bb)
{
    int i = blockIdx.x * 256 + threadIdx.x;
    split_bf16(Wb[i], g_Wb_hi[i], g_Wb_lo[i]);
    if (i < Cd) g_bias_b[i] = bb[i];
    if (i < Bd * Nd) g_u[i] = 0.f;
}

// ---------------------------------------------------------------------------
// prep X: transpose + split: XT[b][n][c] = X[b][c][n]
// ---------------------------------------------------------------------------
__global__ __launch_bounds__(256)
void k_prep_x(const float* __restrict__ X)
{
    __shared__ float t[32][33];
    const int b = blockIdx.z, n0 = blockIdx.x * 32, c0 = blockIdx.y * 32;
    const int tx = threadIdx.x, ty = threadIdx.y;
    #pragma unroll
    for (int r = 0; r < 4; r++)
        t[ty + 8 * r][tx] = X[((size_t)b * Cd + c0 + ty + 8 * r) * Nd + n0 + tx];
    __syncthreads();
    #pragma unroll
    for (int r = 0; r < 4; r++) {
        float v = t[tx][ty + 8 * r];
        size_t o = ((size_t)b * Nd + n0 + ty + 8 * r) * Cd + c0 + tx;
        split_bf16(v, g_XT_hi[o], g_XT_lo[o]);
    }
}

// ---------------------------------------------------------------------------
// row stats of S_eff = g_S + u:  rmax, 1/sum(exp). One block per row.
// ---------------------------------------------------------------------------
__global__ __launch_bounds__(256)
void k_stats()
{
    __shared__ float red[8];
    const int r = blockIdx.x, b = r >> 10;
    const float* p = g_S + (size_t)r * Nd;
    const int tid = threadIdx.x, lane = tid & 31, warp = tid >> 5;

    float4 v = *reinterpret_cast<const float4*>(p + tid * 4);
    float4 uv = *reinterpret_cast<const float4*>(g_u + b * Nd + tid * 4);
    v.x += uv.x; v.y += uv.y; v.z += uv.z; v.w += uv.w;

    float m = fmaxf(fmaxf(v.x, v.y), fmaxf(v.z, v.w));
    #pragma unroll
    for (int o = 16; o; o >>= 1) m = fmaxf(m, __shfl_xor_sync(0xffffffffu, m, o));
    if (lane == 0) red[warp] = m;
    __syncthreads();
    float rowmax = red[0];
    #pragma unroll
    for (int i = 1; i < 8; i++) rowmax = fmaxf(rowmax, red[i]);
    __syncthreads();

    float s = __expf(v.x - rowmax) + __expf(v.y - rowmax)
            + __expf(v.z - rowmax) + __expf(v.w - rowmax);
    #pragma unroll
    for (int o = 16; o; o >>= 1) s += __shfl_xor_sync(0xffffffffu, s, o);
    if (lane == 0) red[warp] = s;
    __syncthreads();
    if (tid == 0) {
        float rowsum = red[0];
        #pragma unroll
        for (int i = 1; i < 8; i++) rowsum += red[i];
        g_rmax[r] = rowmax;
        g_rinv[r] = 1.0f / rowsum;
    }
}

// ---------------------------------------------------------------------------
// trS: AT[b][m][n] = split( exp(S[b][n][m] + u[m] - rmax[n]) * rinv[n] )
// ---------------------------------------------------------------------------
__global__ __launch_bounds__(256)
void k_trS()
{
    __shared__ float t[32][33];
    __shared__ float rm[32], ri[32], uu[32];
    const int b = blockIdx.z, m0 = blockIdx.x * 32, n0 = blockIdx.y * 32;
    const int tx = threadIdx.x, ty = threadIdx.y;
    #pragma unroll
    for (int r = 0; r < 4; r++)
        t[ty + 8 * r][tx] = g_S[((size_t)b * Nd + n0 + ty + 8 * r) * Nd + m0 + tx];
    if (ty == 0) {
        rm[tx] = g_rmax[b * Nd + n0 + tx];
        ri[tx] = g_rinv[b * Nd + n0 + tx];
        uu[tx] = g_u[b * Nd + m0 + tx];
    }
    __syncthreads();
    #pragma unroll
    for (int r = 0; r < 4; r++) {
        const int mj = ty + 8 * r;
        float e = __expf(t[tx][mj] + uu[mj] - rm[tx]) * ri[tx];
        size_t o = ((size_t)b * Nd + m0 + mj) * Nd + n0 + tx;
        split_bf16(e, g_AT_hi[o], g_AT_lo[o]);
    }
}

// ---------------------------------------------------------------------------
// mma.sync GEMM: 256 threads, 8 warps (2x4), warp tile 64x32, CTA 128x128.
// 4-stage cp.async pipeline, BK=16, wait_group 2 (3 tiles in flight),
// 48B-padded smem rows (conflict-free ldmatrix), 2 CTAs/SM.
// MODE 0: M       D[c][k] = WphiT . WthetaT            -> g_M split
// MODE 1: fused:  flat<32: TT = XT.M ; flat>=32: beta = Wb.XT (+bias)
// MODE 2: G       D[n][m] = XT . TT                    -> g_S fp32
// MODE 3: z       D[c][m] = beta . AT  (+X)            -> out fp32
// ---------------------------------------------------------------------------
template <int MODE>
__global__ __launch_bounds__(256, 2)
void k_gemm(const float* __restrict__ Xres, float* __restrict__ Out)
{
    extern __shared__ __align__(128) char smem[];
    const uint32_t sbase = smem_u32(smem);
    const int tid = threadIdx.x;
    const int lane = tid & 31, wid = tid >> 5;
    const int wr = wid >> 2, wc = wid & 3;          // 2x4 warp grid
    const int bz = blockIdx.z;

    int m0, n0;
    bool isTT = true;
    if (MODE == 1) {
        const int flat = blockIdx.y * 8 + blockIdx.x;   // 0..63
        isTT = flat < 32;
        if (isTT) { m0 = (flat >> 2) * 128; n0 = (flat & 3) * 128; }
        else      { const int f2 = flat - 32; m0 = (f2 >> 3) * 128; n0 = (f2 & 7) * 128; }
    } else {
        m0 = blockIdx.y * 128; n0 = blockIdx.x * 128;
    }

    const __nv_bfloat16 *Ah, *Al, *Bh, *Bl;
    int ldA, ldB;
    constexpr int K = (MODE == 3) ? Nd : Cd;
    if (MODE == 0) {
        Ah = g_WT_hi;               Al = g_WT_lo;
        Bh = g_WT_hi + Cd * Cd;     Bl = g_WT_lo + Cd * Cd;
        ldA = Cd; ldB = Cd;
    } else if (MODE == 1) {
        if (isTT) {
            Ah = g_XT_hi + (size_t)bz * Nd * Cd;  Al = g_XT_lo + (size_t)bz * Nd * Cd;
            Bh = g_M_hi;                          Bl = g_M_lo;
        } else {
            Ah = g_Wb_hi;                         Al = g_Wb_lo;
            Bh = g_XT_hi + (size_t)bz * Nd * Cd;  Bl = g_XT_lo + (size_t)bz * Nd * Cd;
        }
        ldA = Cd; ldB = Cd;
    } else if (MODE == 2) {
        Ah = g_XT_hi + (size_t)bz * Nd * Cd;  Al = g_XT_lo + (size_t)bz * Nd * Cd;
        Bh = g_TT_hi + (size_t)bz * Nd * Cd;  Bl = g_TT_lo + (size_t)bz * Nd * Cd;
        ldA = Cd; ldB = Cd;
    } else {
        Ah = g_beta_hi + (size_t)bz * Cd * Nd;  Al = g_beta_lo + (size_t)bz * Cd * Nd;
        Bh = g_AT_hi + (size_t)bz * Nd * Nd;    Bl = g_AT_lo + (size_t)bz * Nd * Nd;
        ldA = Nd; ldB = Nd;
    }

    // loader role: quarter oh -> one operand-half; 4 cp16 per thread / stage
    const int oh = tid >> 6, lt = tid & 63;
    const __nv_bfloat16* src;
    int row0, ld;
    if      (oh == 0) { src = Ah; row0 = m0; ld = ldA; }
    else if (oh == 1) { src = Al; row0 = m0; ld = ldA; }
    else if (oh == 2) { src = Bh; row0 = n0; ld = ldB; }
    else              { src = Bl; row0 = n0; ld = ldB; }

    auto cp_tile = [&](int buf, int k0) {
        const uint32_t sb = sbase + buf * BUF_B + oh * TILE_B;
        #pragma unroll
        for (int i = 0; i < 4; i++) {
            const int j = i * 64 + lt;
            const int row = j >> 1, c = j & 1;       // 2 chunks of 16B per row
            cp16(sb + row * ROWB + c * 16,
                 src + (size_t)(row0 + row) * ld + k0 + c * 8);
        }
        cp_commit();
    };

    float acc[4][4][4];
    #pragma unroll
    for (int i = 0; i < 4; i++)
        #pragma unroll
        for (int j = 0; j < 4; j++)
            #pragma unroll
            for (int q = 0; q < 4; q++) acc[i][j][q] = 0.f;

    // ldmatrix lane address components
    const int a_r = lane & 15, a_c = lane >> 4;      // A: rows 0-15, k-chunk
    const int b_r = (lane & 7) + ((lane & 16) >> 1); // B: n within 16
    const int b_c = (lane >> 3) & 1;                 // B: k-chunk

    // prologue: 3 stages in flight
    cp_tile(0, 0);
    cp_tile(1, BK);
    cp_tile(2, 2 * BK);

    constexpr int NT = K / BK;
    for (int t = 0; t < NT; t++) {
        cp_wait2();                 // tile t complete (3 groups always pending)
        __syncthreads();
        if (t + 3 < NT) cp_tile((t + 3) & 3, (t + 3) * BK);
        else            cp_commit();   // keep group-count invariant

        const uint32_t sAh = sbase + (t & 3) * BUF_B;
        const uint32_t sAl = sAh + TILE_B;
        const uint32_t sBh = sAh + 2 * TILE_B;
        const uint32_t sBl = sAh + 3 * TILE_B;

        uint32_t bhi[4][2], blo[4][2];
        #pragma unroll
        for (int p = 0; p < 2; p++) {
            const uint32_t off = (uint32_t)(wc * 32 + p * 16 + b_r) * ROWB + b_c * 16;
            uint32_t th[4], tl[4];
            ldm_x4(th, sBh + off);
            ldm_x4(tl, sBl + off);
            bhi[2 * p][0] = th[0]; bhi[2 * p][1] = th[1];
            bhi[2 * p + 1][0] = th[2]; bhi[2 * p + 1][1] = th[3];
            blo[2 * p][0] = tl[0]; blo[2 * p][1] = tl[1];
            blo[2 * p + 1][0] = tl[2]; blo[2 * p + 1][1] = tl[3];
        }
        #pragma unroll
        for (int mt = 0; mt < 4; mt++) {
            uint32_t ahi[4], alo[4];
            const uint32_t off = (uint32_t)(wr * 64 + mt * 16 + a_r) * ROWB + a_c * 16;
            ldm_x4(ahi, sAh + off);
            ldm_x4(alo, sAl + off);
            #pragma unroll
            for (int nt = 0; nt < 4; nt++) {
                mma_bf16(acc[mt][nt], ahi, bhi[nt][0], bhi[nt][1]);
                mma_bf16(acc[mt][nt], ahi, blo[nt][0], blo[nt][1]);
                mma_bf16(acc[mt][nt], alo, bhi[nt][0], bhi[nt][1]);
            }
        }
    }

    // epilogue: fragment lane -> (row = lane>>2 [+8], cols (lane&3)*2, +1)
    #pragma unroll
    for (int mt = 0; mt < 4; mt++)
        #pragma unroll
        for (int nt = 0; nt < 4; nt++) {
            const int row = m0 + wr * 64 + mt * 16 + (lane >> 2);
            const int col = n0 + wc * 32 + nt * 8 + (lane & 3) * 2;
            const float* d = acc[mt][nt];

            if (MODE == 0 || MODE == 1) {
                float q0 = d[0], q1 = d[1], q2 = d[2], q3 = d[3];
                __nv_bfloat16 *dh, *dl;
                size_t o0;
                int ldo;
                if (MODE == 0) {
                    ldo = Cd; o0 = (size_t)row * ldo + col;
                    dh = g_M_hi; dl = g_M_lo;
                } else if (isTT) {
                    ldo = Cd; o0 = ((size_t)bz * Nd + row) * ldo + col;
                    dh = g_TT_hi; dl = g_TT_lo;
                } else {
                    q0 += g_bias_b[row];     q1 += g_bias_b[row];
                    q2 += g_bias_b[row + 8]; q3 += g_bias_b[row + 8];
                    ldo = Nd; o0 = ((size_t)bz * Cd + row) * ldo + col;
                    dh = g_beta_hi; dl = g_beta_lo;
                }
                __nv_bfloat16 h0, l0, h1, l1, h2, l2, h3, l3;
                split_bf16(q0, h0, l0); split_bf16(q1, h1, l1);
                split_bf16(q2, h2, l2); split_bf16(q3, h3, l3);
                const size_t o1 = o0 + 8 * (size_t)ldo;
                *reinterpret_cast<uint32_t*>(dh + o0) =
                    (uint32_t)__bfloat16_as_ushort(h0) | ((uint32_t)__bfloat16_as_ushort(h1) << 16);
                *reinterpret_cast<uint32_t*>(dl + o0) =
                    (uint32_t)__bfloat16_as_ushort(l0) | ((uint32_t)__bfloat16_as_ushort(l1) << 16);
                *reinterpret_cast<uint32_t*>(dh + o1) =
                    (uint32_t)__bfloat16_as_ushort(h2) | ((uint32_t)__bfloat16_as_ushort(h3) << 16);
                *reinterpret_cast<uint32_t*>(dl + o1) =
                    (uint32_t)__bfloat16_as_ushort(l2) | ((uint32_t)__bfloat16_as_ushort(l3) << 16);
            } else if (MODE == 2) {
                const size_t o0 = ((size_t)bz * Nd + row) * Nd + col;
                *reinterpret_cast<float2*>(g_S + o0) = make_float2(d[0], d[1]);
                *reinterpret_cast<float2*>(g_S + o0 + 8 * Nd) = make_float2(d[2], d[3]);
            } else {
                const size_t o0 = ((size_t)bz * Cd + row) * Nd + col;
                const size_t o1 = o0 + 8 * Nd;
                float2 x0 = *reinterpret_cast<const float2*>(Xres + o0);
                float2 x1 = *reinterpret_cast<const float2*>(Xres + o1);
                *reinterpret_cast<float2*>(Out + o0) = make_float2(d[0] + x0.x, d[1] + x0.y);
                *reinterpret_cast<float2*>(Out + o1) = make_float2(d[2] + x1.x, d[3] + x1.y);
            }
        }
}

// ---------------------------------------------------------------------------
extern "C" void kernel_launch(void* const* d_in, const int* in_sizes, int n_in,
                              void* d_out, int out_size)
{
    (void)in_sizes; (void)n_in; (void)out_size;
    const float* X  = (const float*)d_in[0];
    const float* Wp = (const float*)d_in[1];
    const float* bp = (const float*)d_in[2];
    const float* Wt = (const float*)d_in[3];
    const float* bt = (const float*)d_in[4];
    const float* Wb = (const float*)d_in[5];
    const float* bb = (const float*)d_in[6];
    float* out = (float*)d_out;
    (void)bt;

    static bool attr_done = false;
    if (!attr_done) {
        cudaFuncSetAttribute(k_gemm<0>, cudaFuncAttributeMaxDynamicSharedMemorySize, SM_TOTAL);
        cudaFuncSetAttribute(k_gemm<1>, cudaFuncAttributeMaxDynamicSharedMemorySize, SM_TOTAL);
        cudaFuncSetAttribute(k_gemm<2>, cudaFuncAttributeMaxDynamicSharedMemorySize, SM_TOTAL);
        cudaFuncSetAttribute(k_gemm<3>, cudaFuncAttributeMaxDynamicSharedMemorySize, SM_TOTAL);
        attr_done = true;
    }

    k_prep_wb<<<(Cd * Cd) / 256, 256>>>(Wb, bb);                     // + zero g_u
    k_v      <<<16, 256>>>(Wt, bp);
    k_prep_wt<<<dim3(16, 16, 2), dim3(32, 8)>>>(Wp, Wt);
    k_prep_x <<<dim3(Nd / 32, Cd / 32, Bd), dim3(32, 8)>>>(X);
    k_u      <<<dim3(32, 8), 256>>>(X);
    k_gemm<0><<<dim3(4, 4, 1), 256, SM_TOTAL>>>(nullptr, nullptr);   // M
    k_gemm<1><<<dim3(8, 8, Bd), 256, SM_TOTAL>>>(nullptr, nullptr);  // TT + beta fused
    k_gemm<2><<<dim3(8, 8, Bd), 256, SM_TOTAL>>>(nullptr, nullptr);  // G -> g_S
    k_stats  <<<Bd * Nd, 256>>>();
    k_trS    <<<dim3(Nd / 32, Nd / 32, Bd), dim3(32, 8)>>>();
    k_gemm<3><<<dim3(8, 4, Bd), 256, SM_TOTAL>>>(X, out);            // z -> out
}

// round 13
// speedup vs baseline: 1.2130x; 1.2130x over previous
#include <cuda_runtime.h>
#include <cuda_bf16.h>
#include <cstdint>

// ---------------------------------------------------------------------------
// Non-local attention block, B=8, C=512, N=1024 (H=W=32), fp32 in/out.
// R12: R10 engine (BK=32, 64x32 warp tiles, one sync/k-tile) with
//      swizzled 64B smem rows (Swizzle<3,4,3>, conflict-free ldmatrix)
//      -> stage = 32KB -> 3-stage cp.async pipeline at 2 CTAs/SM.
// ---------------------------------------------------------------------------

namespace {
constexpr int Cd = 512, Nd = 1024, Bd = 8;
constexpr int ROWB   = 64;                 // 32 bf16 = 64B data, swizzled (no pad)
constexpr int TILE_B = 128 * ROWB;         // 8192 B per operand-half tile
constexpr int BUF_B  = 4 * TILE_B;         // Ahi,Alo,Bhi,Blo = 32768 per stage
constexpr int STAGES = 3;
constexpr int SM_TOTAL = STAGES * BUF_B;   // 98304 -> 2 CTAs/SM
}

__device__ __forceinline__ uint32_t swz(uint32_t off) {
    return off ^ ((off >> 3) & 0x70);      // Swizzle<3,4,3> on 64B rows
}

// ---- device scratch --------------------------------------------------------
__device__ __nv_bfloat16 g_XT_hi[Bd * Nd * Cd];    // [b][n][c]
__device__ __nv_bfloat16 g_XT_lo[Bd * Nd * Cd];
__device__ __nv_bfloat16 g_WT_hi[2 * Cd * Cd];     // rows 0-511 WphiT, 512-1023 WthetaT
__device__ __nv_bfloat16 g_WT_lo[2 * Cd * Cd];
__device__ __nv_bfloat16 g_Wb_hi[Cd * Cd];         // Wbeta row-major [c][k]
__device__ __nv_bfloat16 g_Wb_lo[Cd * Cd];
__device__ float         g_bias_b[Cd];
__device__ float         g_v[Cd];                  // Wtheta^T bphi
__device__ float         g_u[Bd * Nd];             // v^T X_b
__device__ float         g_rmax[Bd * Nd];          // row max of S_eff
__device__ float         g_rinv[Bd * Nd];          // 1 / row sum exp
__device__ __nv_bfloat16 g_M_hi[Cd * Cd];          // [c][k]
__device__ __nv_bfloat16 g_M_lo[Cd * Cd];
__device__ __nv_bfloat16 g_TT_hi[Bd * Nd * Cd];    // [b][m][c]
__device__ __nv_bfloat16 g_TT_lo[Bd * Nd * Cd];
__device__ __nv_bfloat16 g_beta_hi[Bd * Cd * Nd];  // [b][c][n]
__device__ __nv_bfloat16 g_beta_lo[Bd * Cd * Nd];
__device__ float         g_S[Bd * Nd * Nd];        // [b][n][m]
__device__ __nv_bfloat16 g_AT_hi[Bd * Nd * Nd];    // [b][m][n]
__device__ __nv_bfloat16 g_AT_lo[Bd * Nd * Nd];

// ---- helpers ---------------------------------------------------------------
__device__ __forceinline__ uint32_t smem_u32(const void* p) {
    uint32_t a;
    asm("{ .reg .u64 t; cvta.to.shared.u64 t, %1; cvt.u32.u64 %0, t; }"
        : "=r"(a) : "l"(p));
    return a;
}
__device__ __forceinline__ void cp16(uint32_t dst, const void* src) {
    asm volatile("cp.async.cg.shared.global [%0], [%1], 16;"
                 :: "r"(dst), "l"(__cvta_generic_to_global(src)) : "memory");
}
__device__ __forceinline__ void cp_commit() {
    asm volatile("cp.async.commit_group;" ::: "memory");
}
__device__ __forceinline__ void cp_wait1() {
    asm volatile("cp.async.wait_group 1;" ::: "memory");
}
__device__ __forceinline__ void ldm_x4(uint32_t (&r)[4], uint32_t addr) {
    asm volatile("ldmatrix.sync.aligned.m8n8.x4.shared.b16 {%0,%1,%2,%3}, [%4];"
        : "=r"(r[0]), "=r"(r[1]), "=r"(r[2]), "=r"(r[3]) : "r"(addr));
}
__device__ __forceinline__ void mma_bf16(float (&d)[4], const uint32_t (&a)[4],
                                         const uint32_t b0, const uint32_t b1) {
    asm volatile(
        "mma.sync.aligned.m16n8k16.row.col.f32.bf16.bf16.f32 "
        "{%0,%1,%2,%3},{%4,%5,%6,%7},{%8,%9},{%0,%1,%2,%3};"
        : "+f"(d[0]), "+f"(d[1]), "+f"(d[2]), "+f"(d[3])
        : "r"(a[0]), "r"(a[1]), "r"(a[2]), "r"(a[3]), "r"(b0), "r"(b1));
}
__device__ __forceinline__ void split_bf16(float v, __nv_bfloat16& h, __nv_bfloat16& l) {
    h = __float2bfloat16(v);
    l = __float2bfloat16(v - __bfloat162float(h));
}

// ---------------------------------------------------------------------------
// v[i] = sum_q Wt[q][i] * bphi[q]  — atomic-free
// ---------------------------------------------------------------------------
__global__ __launch_bounds__(256)
void k_v(const float* __restrict__ Wt, const float* __restrict__ bphi)
{
    __shared__ float part[8][32];
    const int i  = blockIdx.x * 32 + (threadIdx.x & 31);
    const int qs = threadIdx.x >> 5;
    float s = 0.f;
    #pragma unroll 8
    for (int r = 0; r < 64; r++) {
        const int q = qs * 64 + r;
        s += Wt[(size_t)q * Cd + i] * bphi[q];
    }
    part[qs][threadIdx.x & 31] = s;
    __syncthreads();
    if (qs == 0) {
        float t = part[0][threadIdx.x];
        #pragma unroll
        for (int w = 1; w < 8; w++) t += part[w][threadIdx.x];
        g_v[i] = t;
    }
}

// ---------------------------------------------------------------------------
// u[b][m] += sum_{k in chunk} v[k] * X[b][k][m]   (g_u zeroed by k_prep_wb)
// ---------------------------------------------------------------------------
__global__ __launch_bounds__(256)
void k_u(const float* __restrict__ X)
{
    __shared__ float vs[64];
    const int kc = blockIdx.y;
    if (threadIdx.x < 64) vs[threadIdx.x] = g_v[kc * 64 + threadIdx.x];
    __syncthreads();
    const int g = blockIdx.x * 256 + threadIdx.x;
    const int b = g >> 10, m = g & 1023;
    const float* xp = X + ((size_t)b * Cd + kc * 64) * Nd + m;
    float s = 0.f;
    #pragma unroll 8
    for (int k = 0; k < 64; k++) s += vs[k] * xp[(size_t)k * Nd];
    atomicAdd(&g_u[g], s);
}

// ---------------------------------------------------------------------------
// prep WT: transpose + split Wphi, Wtheta
// ---------------------------------------------------------------------------
__global__ __launch_bounds__(256)
void k_prep_wt(const float* __restrict__ Wp, const float* __restrict__ Wt)
{
    __shared__ float t[32][33];
    const float* W = (blockIdx.z == 0) ? Wp : Wt;
    const int r0 = blockIdx.x * 32, q0 = blockIdx.y * 32;
    const int tx = threadIdx.x, ty = threadIdx.y;
    #pragma unroll
    for (int r = 0; r < 4; r++)
        t[ty + 8 * r][tx] = W[(size_t)(q0 + ty + 8 * r) * Cd + r0 + tx];
    __syncthreads();
    #pragma unroll
    for (int r = 0; r < 4; r++) {
        float v = t[tx][ty + 8 * r];
        size_t o = ((size_t)blockIdx.z * Cd + r0 + ty + 8 * r) * Cd + q0 + tx;
        split_bf16(v, g_WT_hi[o], g_WT_lo[o]);
    }
}

// ---------------------------------------------------------------------------
// prep Wb: row-major split + beta bias copy + zero g_u
// ---------------------------------------------------------------------------
__global__ __launch_bounds__(256)
void k_prep_wb(const float* __restrict__ Wb, const float* __restrict__ bb)
{
    int i = blockIdx.x * 256 + threadIdx.x;
    split_bf16(Wb[i], g_Wb_hi[i], g_Wb_lo[i]);
    if (i < Cd) g_bias_b[i] = bb[i];
    if (i < Bd * Nd) g_u[i] = 0.f;
}

// ---------------------------------------------------------------------------
// prep X: transpose + split: XT[b][n][c] = X[b][c][n]
// ---------------------------------------------------------------------------
__global__ __launch_bounds__(256)
void k_prep_x(const float* __restrict__ X)
{
    __shared__ float t[32][33];
    const int b = blockIdx.z, n0 = blockIdx.x * 32, c0 = blockIdx.y * 32;
    const int tx = threadIdx.x, ty = threadIdx.y;
    #pragma unroll
    for (int r = 0; r < 4; r++)
        t[ty + 8 * r][tx] = X[((size_t)b * Cd + c0 + ty + 8 * r) * Nd + n0 + tx];
    __syncthreads();
    #pragma unroll
    for (int r = 0; r < 4; r++) {
        float v = t[tx][ty + 8 * r];
        size_t o = ((size_t)b * Nd + n0 + ty + 8 * r) * Cd + c0 + tx;
        split_bf16(v, g_XT_hi[o], g_XT_lo[o]);
    }
}

// ---------------------------------------------------------------------------
// row stats of S_eff = g_S + u:  rmax, 1/sum(exp). One block per row.
// ---------------------------------------------------------------------------
__global__ __launch_bounds__(256)
void k_stats()
{
    __shared__ float red[8];
    const int r = blockIdx.x, b = r >> 10;
    const float* p = g_S + (size_t)r * Nd;
    const int tid = threadIdx.x, lane = tid & 31, warp = tid >> 5;

    float4 v = *reinterpret_cast<const float4*>(p + tid * 4);
    float4 uv = *reinterpret_cast<const float4*>(g_u + b * Nd + tid * 4);
    v.x += uv.x; v.y += uv.y; v.z += uv.z; v.w += uv.w;

    float m = fmaxf(fmaxf(v.x, v.y), fmaxf(v.z, v.w));
    #pragma unroll
    for (int o = 16; o; o >>= 1) m = fmaxf(m, __shfl_xor_sync(0xffffffffu, m, o));
    if (lane == 0) red[warp] = m;
    __syncthreads();
    float rowmax = red[0];
    #pragma unroll
    for (int i = 1; i < 8; i++) rowmax = fmaxf(rowmax, red[i]);
    __syncthreads();

    float s = __expf(v.x - rowmax) + __expf(v.y - rowmax)
            + __expf(v.z - rowmax) + __expf(v.w - rowmax);
    #pragma unroll
    for (int o = 16; o; o >>= 1) s += __shfl_xor_sync(0xffffffffu, s, o);
    if (lane == 0) red[warp] = s;
    __syncthreads();
    if (tid == 0) {
        float rowsum = red[0];
        #pragma unroll
        for (int i = 1; i < 8; i++) rowsum += red[i];
        g_rmax[r] = rowmax;
        g_rinv[r] = 1.0f / rowsum;
    }
}

// ---------------------------------------------------------------------------
// trS: AT[b][m][n] = split( exp(S[b][n][m] + u[m] - rmax[n]) * rinv[n] )
// ---------------------------------------------------------------------------
__global__ __launch_bounds__(256)
void k_trS()
{
    __shared__ float t[32][33];
    __shared__ float rm[32], ri[32], uu[32];
    const int b = blockIdx.z, m0 = blockIdx.x * 32, n0 = blockIdx.y * 32;
    const int tx = threadIdx.x, ty = threadIdx.y;
    #pragma unroll
    for (int r = 0; r < 4; r++)
        t[ty + 8 * r][tx] = g_S[((size_t)b * Nd + n0 + ty + 8 * r) * Nd + m0 + tx];
    if (ty == 0) {
        rm[tx] = g_rmax[b * Nd + n0 + tx];
        ri[tx] = g_rinv[b * Nd + n0 + tx];
        uu[tx] = g_u[b * Nd + m0 + tx];
    }
    __syncthreads();
    #pragma unroll
    for (int r = 0; r < 4; r++) {
        const int mj = ty + 8 * r;
        float e = __expf(t[tx][mj] + uu[mj] - rm[tx]) * ri[tx];
        size_t o = ((size_t)b * Nd + m0 + mj) * Nd + n0 + tx;
        split_bf16(e, g_AT_hi[o], g_AT_lo[o]);
    }
}

// ---------------------------------------------------------------------------
// mma.sync GEMM: 256 threads, 8 warps (2x4), warp tile 64x32, CTA 128x128.
// BK=32, 3-stage cp.async pipeline (wait_group 1, 2 tiles in flight),
// swizzled 64B rows (conflict-free ldmatrix), 2 CTAs/SM.
// MODE 0: M       D[c][k] = WphiT . WthetaT            -> g_M split
// MODE 1: fused:  flat<32: TT = XT.M ; flat>=32: beta = Wb.XT (+bias)
// MODE 2: G       D[n][m] = XT . TT                    -> g_S fp32
// MODE 3: z       D[c][m] = beta . AT  (+X)            -> out fp32
// ---------------------------------------------------------------------------
template <int MODE>
__global__ __launch_bounds__(256, 2)
void k_gemm(const float* __restrict__ Xres, float* __restrict__ Out)
{
    extern __shared__ __align__(1024) char smem[];
    const uint32_t sbase = smem_u32(smem);
    const int tid = threadIdx.x;
    const int lane = tid & 31, wid = tid >> 5;
    const int wr = wid >> 2, wc = wid & 3;          // 2x4 warp grid
    const int bz = blockIdx.z;

    int m0, n0;
    bool isTT = true;
    if (MODE == 1) {
        const int flat = blockIdx.y * 8 + blockIdx.x;   // 0..63
        isTT = flat < 32;
        if (isTT) { m0 = (flat >> 2) * 128; n0 = (flat & 3) * 128; }
        else      { const int f2 = flat - 32; m0 = (f2 >> 3) * 128; n0 = (f2 & 7) * 128; }
    } else {
        m0 = blockIdx.y * 128; n0 = blockIdx.x * 128;
    }

    const __nv_bfloat16 *Ah, *Al, *Bh, *Bl;
    int ldA, ldB;
    constexpr int K = (MODE == 3) ? Nd : Cd;
    if (MODE == 0) {
        Ah = g_WT_hi;               Al = g_WT_lo;
        Bh = g_WT_hi + Cd * Cd;     Bl = g_WT_lo + Cd * Cd;
        ldA = Cd; ldB = Cd;
    } else if (MODE == 1) {
        if (isTT) {
            Ah = g_XT_hi + (size_t)bz * Nd * Cd;  Al = g_XT_lo + (size_t)bz * Nd * Cd;
            Bh = g_M_hi;                          Bl = g_M_lo;
        } else {
            Ah = g_Wb_hi;                         Al = g_Wb_lo;
            Bh = g_XT_hi + (size_t)bz * Nd * Cd;  Bl = g_XT_lo + (size_t)bz * Nd * Cd;
        }
        ldA = Cd; ldB = Cd;
    } else if (MODE == 2) {
        Ah = g_XT_hi + (size_t)bz * Nd * Cd;  Al = g_XT_lo + (size_t)bz * Nd * Cd;
        Bh = g_TT_hi + (size_t)bz * Nd * Cd;  Bl = g_TT_lo + (size_t)bz * Nd * Cd;
        ldA = Cd; ldB = Cd;
    } else {
        Ah = g_beta_hi + (size_t)bz * Cd * Nd;  Al = g_beta_lo + (size_t)bz * Cd * Nd;
        Bh = g_AT_hi + (size_t)bz * Nd * Nd;    Bl = g_AT_lo + (size_t)bz * Nd * Nd;
        ldA = Nd; ldB = Nd;
    }

    // loader role: quarter oh -> one operand-half; 8 cp.async per k-tile
    const int oh = tid >> 6, lt = tid & 63;
    const __nv_bfloat16* src;
    int row0, ld;
    if      (oh == 0) { src = Ah; row0 = m0; ld = ldA; }
    else if (oh == 1) { src = Al; row0 = m0; ld = ldA; }
    else if (oh == 2) { src = Bh; row0 = n0; ld = ldB; }
    else              { src = Bl; row0 = n0; ld = ldB; }

    auto cp_tile = [&](int buf, int k0) {
        const uint32_t sb = sbase + buf * BUF_B + oh * TILE_B;
        #pragma unroll
        for (int i = 0; i < 8; i++) {
            const int j = i * 64 + lt;
            const int row = j >> 2, c = j & 3;
            cp16(sb + swz(row * ROWB + c * 16),
                 src + (size_t)(row0 + row) * ld + k0 + c * 8);
        }
        cp_commit();
    };

    float acc[4][4][4];
    #pragma unroll
    for (int i = 0; i < 4; i++)
        #pragma unroll
        for (int j = 0; j < 4; j++)
            #pragma unroll
            for (int q = 0; q < 4; q++) acc[i][j][q] = 0.f;

    // ldmatrix lane address components
    const int a_r = lane & 15, a_c = lane >> 4;
    const int b_r = (lane & 7) + ((lane & 16) >> 1);
    const int b_c = (lane >> 3) & 1;

    // prologue: 2 stages in flight
    cp_tile(0, 0);
    cp_tile(1, 32);

    constexpr int NT = K / 32;
    int buf = 0;
    for (int t = 0; t < NT; t++) {
        cp_wait1();                 // tile t complete (<=1 group pending)
        __syncthreads();
        if (t + 2 < NT) cp_tile((buf + 2) % 3, (t + 2) * 32);
        else            cp_commit();   // keep group-count invariant

        const uint32_t sAh = sbase + buf * BUF_B;
        const uint32_t sAl = sAh + TILE_B;
        const uint32_t sBh = sAh + 2 * TILE_B;
        const uint32_t sBl = sAh + 3 * TILE_B;

        #pragma unroll
        for (int ks = 0; ks < 2; ks++) {
            uint32_t bhi[4][2], blo[4][2];
            #pragma unroll
            for (int p = 0; p < 2; p++) {
                const uint32_t off = swz((uint32_t)(wc * 32 + p * 16 + b_r) * ROWB
                                         + (uint32_t)(ks * 2 + b_c) * 16);
                uint32_t th[4], tl[4];
                ldm_x4(th, sBh + off);
                ldm_x4(tl, sBl + off);
                bhi[2 * p][0] = th[0]; bhi[2 * p][1] = th[1];
                bhi[2 * p + 1][0] = th[2]; bhi[2 * p + 1][1] = th[3];
                blo[2 * p][0] = tl[0]; blo[2 * p][1] = tl[1];
                blo[2 * p + 1][0] = tl[2]; blo[2 * p + 1][1] = tl[3];
            }
            #pragma unroll
            for (int mt = 0; mt < 4; mt++) {
                uint32_t ahi[4], alo[4];
                const uint32_t off = swz((uint32_t)(wr * 64 + mt * 16 + a_r) * ROWB
                                         + (uint32_t)(ks * 2 + a_c) * 16);
                ldm_x4(ahi, sAh + off);
                ldm_x4(alo, sAl + off);
                #pragma unroll
                for (int nt = 0; nt < 4; nt++) {
                    mma_bf16(acc[mt][nt], ahi, bhi[nt][0], bhi[nt][1]);
                    mma_bf16(acc[mt][nt], ahi, blo[nt][0], blo[nt][1]);
                    mma_bf16(acc[mt][nt], alo, bhi[nt][0], bhi[nt][1]);
                }
            }
        }
        buf = (buf + 1) % 3;
    }

    // epilogue: fragment lane -> (row = lane>>2 [+8], cols (lane&3)*2, +1)
    #pragma unroll
    for (int mt = 0; mt < 4; mt++)
        #pragma unroll
        for (int nt = 0; nt < 4; nt++) {
            const int row = m0 + wr * 64 + mt * 16 + (lane >> 2);
            const int col = n0 + wc * 32 + nt * 8 + (lane & 3) * 2;
            const float* d = acc[mt][nt];

            if (MODE == 0 || MODE == 1) {
                float q0 = d[0], q1 = d[1], q2 = d[2], q3 = d[3];
                __nv_bfloat16 *dh, *dl;
                size_t o0;
                int ldo;
                if (MODE == 0) {
                    ldo = Cd; o0 = (size_t)row * ldo + col;
                    dh = g_M_hi; dl = g_M_lo;
                } else if (isTT) {
                    ldo = Cd; o0 = ((size_t)bz * Nd + row) * ldo + col;
                    dh = g_TT_hi; dl = g_TT_lo;
                } else {
                    q0 += g_bias_b[row];     q1 += g_bias_b[row];
                    q2 += g_bias_b[row + 8]; q3 += g_bias_b[row + 8];
                    ldo = Nd; o0 = ((size_t)bz * Cd + row) * ldo + col;
                    dh = g_beta_hi; dl = g_beta_lo;
                }
                __nv_bfloat16 h0, l0, h1, l1, h2, l2, h3, l3;
                split_bf16(q0, h0, l0); split_bf16(q1, h1, l1);
                split_bf16(q2, h2, l2); split_bf16(q3, h3, l3);
                const size_t o1 = o0 + 8 * (size_t)ldo;
                *reinterpret_cast<uint32_t*>(dh + o0) =
                    (uint32_t)__bfloat16_as_ushort(h0) | ((uint32_t)__bfloat16_as_ushort(h1) << 16);
                *reinterpret_cast<uint32_t*>(dl + o0) =
                    (uint32_t)__bfloat16_as_ushort(l0) | ((uint32_t)__bfloat16_as_ushort(l1) << 16);
                *reinterpret_cast<uint32_t*>(dh + o1) =
                    (uint32_t)__bfloat16_as_ushort(h2) | ((uint32_t)__bfloat16_as_ushort(h3) << 16);
                *reinterpret_cast<uint32_t*>(dl + o1) =
                    (uint32_t)__bfloat16_as_ushort(l2) | ((uint32_t)__bfloat16_as_ushort(l3) << 16);
            } else if (MODE == 2) {
                const size_t o0 = ((size_t)bz * Nd + row) * Nd + col;
                *reinterpret_cast<float2*>(g_S + o0) = make_float2(d[0], d[1]);
                *reinterpret_cast<float2*>(g_S + o0 + 8 * Nd) = make_float2(d[2], d[3]);
            } else {
                const size_t o0 = ((size_t)bz * Cd + row) * Nd + col;
                const size_t o1 = o0 + 8 * Nd;
                float2 x0 = *reinterpret_cast<const float2*>(Xres + o0);
                float2 x1 = *reinterpret_cast<const float2*>(Xres + o1);
                *reinterpret_cast<float2*>(Out + o0) = make_float2(d[0] + x0.x, d[1] + x0.y);
                *reinterpret_cast<float2*>(Out + o1) = make_float2(d[2] + x1.x, d[3] + x1.y);
            }
        }
}

// ---------------------------------------------------------------------------
extern "C" void kernel_launch(void* const* d_in, const int* in_sizes, int n_in,
                              void* d_out, int out_size)
{
    (void)in_sizes; (void)n_in; (void)out_size;
    const float* X  = (const float*)d_in[0];
    const float* Wp = (const float*)d_in[1];
    const float* bp = (const float*)d_in[2];
    const float* Wt = (const float*)d_in[3];
    const float* bt = (const float*)d_in[4];
    const float* Wb = (const float*)d_in[5];
    const float* bb = (const float*)d_in[6];
    float* out = (float*)d_out;
    (void)bt;

    static bool attr_done = false;
    if (!attr_done) {
        cudaFuncSetAttribute(k_gemm<0>, cudaFuncAttributeMaxDynamicSharedMemorySize, SM_TOTAL);
        cudaFuncSetAttribute(k_gemm<1>, cudaFuncAttributeMaxDynamicSharedMemorySize, SM_TOTAL);
        cudaFuncSetAttribute(k_gemm<2>, cudaFuncAttributeMaxDynamicSharedMemorySize, SM_TOTAL);
        cudaFuncSetAttribute(k_gemm<3>, cudaFuncAttributeMaxDynamicSharedMemorySize, SM_TOTAL);
        attr_done = true;
    }

    k_prep_wb<<<(Cd * Cd) / 256, 256>>>(Wb, bb);                     // + zero g_u
    k_v      <<<16, 256>>>(Wt, bp);
    k_prep_wt<<<dim3(16, 16, 2), dim3(32, 8)>>>(Wp, Wt);
    k_prep_x <<<dim3(Nd / 32, Cd / 32, Bd), dim3(32, 8)>>>(X);
    k_u      <<<dim3(32, 8), 256>>>(X);
    k_gemm<0><<<dim3(4, 4, 1), 256, SM_TOTAL>>>(nullptr, nullptr);   // M
    k_gemm<1><<<dim3(8, 8, Bd), 256, SM_TOTAL>>>(nullptr, nullptr);  // TT + beta fused
    k_gemm<2><<<dim3(8, 8, Bd), 256, SM_TOTAL>>>(nullptr, nullptr);  // G -> g_S
    k_stats  <<<Bd * Nd, 256>>>();
    k_trS    <<<dim3(Nd / 32, Nd / 32, Bd), dim3(32, 8)>>>();
    k_gemm<3><<<dim3(8, 4, Bd), 256, SM_TOTAL>>>(X, out);            // z -> out
}

// round 14
// speedup vs baseline: 1.2925x; 1.0655x over previous
#include <cuda_runtime.h>
#include <cuda_bf16.h>
#include <cstdint>

// ---------------------------------------------------------------------------
// Non-local attention block, B=8, C=512, N=1024 (H=W=32), fp32 in/out.
// R13: R12 engine (BK=32, swizzled 64B rows, 3-stage cp.async, 2 CTAs/SM)
//      + split-K M GEMM (64 CTAs + reduce)  + softmax partial-stats fused
//      into the G epilogue (k_stats' 32MB re-read eliminated).
// ---------------------------------------------------------------------------

namespace {
constexpr int Cd = 512, Nd = 1024, Bd = 8;
constexpr int ROWB   = 64;                 // 32 bf16 = 64B data, swizzled
constexpr int TILE_B = 128 * ROWB;         // 8192 B per operand-half tile
constexpr int BUF_B  = 4 * TILE_B;         // Ahi,Alo,Bhi,Blo = 32768 per stage
constexpr int STAGES = 3;
constexpr int SM_TOTAL = STAGES * BUF_B;   // 98304 -> 2 CTAs/SM
}

__device__ __forceinline__ uint32_t swz(uint32_t off) {
    return off ^ ((off >> 3) & 0x70);      // Swizzle<3,4,3> on 64B rows
}

// ---- device scratch --------------------------------------------------------
__device__ __nv_bfloat16 g_XT_hi[Bd * Nd * Cd];    // [b][n][c]
__device__ __nv_bfloat16 g_XT_lo[Bd * Nd * Cd];
__device__ __nv_bfloat16 g_WT_hi[2 * Cd * Cd];     // rows 0-511 WphiT, 512-1023 WthetaT
__device__ __nv_bfloat16 g_WT_lo[2 * Cd * Cd];
__device__ __nv_bfloat16 g_Wb_hi[Cd * Cd];         // Wbeta row-major [c][k]
__device__ __nv_bfloat16 g_Wb_lo[Cd * Cd];
__device__ float         g_bias_b[Cd];
__device__ float         g_v[Cd];                  // Wtheta^T bphi
__device__ float         g_u[Bd * Nd];             // v^T X_b
__device__ float         g_rmax[Bd * Nd];          // row max of S_eff
__device__ float         g_rinv[Bd * Nd];          // 1 / row sum exp
__device__ float         g_Mpart[4 * Cd * Cd];     // split-K partials for M
__device__ __nv_bfloat16 g_M_hi[Cd * Cd];          // [c][k]
__device__ __nv_bfloat16 g_M_lo[Cd * Cd];
__device__ __nv_bfloat16 g_TT_hi[Bd * Nd * Cd];    // [b][m][c]
__device__ __nv_bfloat16 g_TT_lo[Bd * Nd * Cd];
__device__ __nv_bfloat16 g_beta_hi[Bd * Cd * Nd];  // [b][c][n]
__device__ __nv_bfloat16 g_beta_lo[Bd * Cd * Nd];
__device__ float         g_S[Bd * Nd * Nd];        // [b][n][m] (G, without u)
__device__ float         g_pmax[Bd * Nd * 8];      // per-row per-coltile max
__device__ float         g_psum[Bd * Nd * 8];      // per-row per-coltile expsum
__device__ __nv_bfloat16 g_AT_hi[Bd * Nd * Nd];    // [b][m][n]
__device__ __nv_bfloat16 g_AT_lo[Bd * Nd * Nd];

// ---- helpers ---------------------------------------------------------------
__device__ __forceinline__ uint32_t smem_u32(const void* p) {
    uint32_t a;
    asm("{ .reg .u64 t; cvta.to.shared.u64 t, %1; cvt.u32.u64 %0, t; }"
        : "=r"(a) : "l"(p));
    return a;
}
__device__ __forceinline__ void cp16(uint32_t dst, const void* src) {
    asm volatile("cp.async.cg.shared.global [%0], [%1], 16;"
                 :: "r"(dst), "l"(__cvta_generic_to_global(src)) : "memory");
}
__device__ __forceinline__ void cp_commit() {
    asm volatile("cp.async.commit_group;" ::: "memory");
}
__device__ __forceinline__ void cp_wait1() {
    asm volatile("cp.async.wait_group 1;" ::: "memory");
}
__device__ __forceinline__ void ldm_x4(uint32_t (&r)[4], uint32_t addr) {
    asm volatile("ldmatrix.sync.aligned.m8n8.x4.shared.b16 {%0,%1,%2,%3}, [%4];"
        : "=r"(r[0]), "=r"(r[1]), "=r"(r[2]), "=r"(r[3]) : "r"(addr));
}
__device__ __forceinline__ void mma_bf16(float (&d)[4], const uint32_t (&a)[4],
                                         const uint32_t b0, const uint32_t b1) {
    asm volatile(
        "mma.sync.aligned.m16n8k16.row.col.f32.bf16.bf16.f32 "
        "{%0,%1,%2,%3},{%4,%5,%6,%7},{%8,%9},{%0,%1,%2,%3};"
        : "+f"(d[0]), "+f"(d[1]), "+f"(d[2]), "+f"(d[3])
        : "r"(a[0]), "r"(a[1]), "r"(a[2]), "r"(a[3]), "r"(b0), "r"(b1));
}
__device__ __forceinline__ void split_bf16(float v, __nv_bfloat16& h, __nv_bfloat16& l) {
    h = __float2bfloat16(v);
    l = __float2bfloat16(v - __bfloat162float(h));
}

// ---------------------------------------------------------------------------
// v[i] = sum_q Wt[q][i] * bphi[q]  — atomic-free
// ---------------------------------------------------------------------------
__global__ __launch_bounds__(256)
void k_v(const float* __restrict__ Wt, const float* __restrict__ bphi)
{
    __shared__ float part[8][32];
    const int i  = blockIdx.x * 32 + (threadIdx.x & 31);
    const int qs = threadIdx.x >> 5;
    float s = 0.f;
    #pragma unroll 8
    for (int r = 0; r < 64; r++) {
        const int q = qs * 64 + r;
        s += Wt[(size_t)q * Cd + i] * bphi[q];
    }
    part[qs][threadIdx.x & 31] = s;
    __syncthreads();
    if (qs == 0) {
        float t = part[0][threadIdx.x];
        #pragma unroll
        for (int w = 1; w < 8; w++) t += part[w][threadIdx.x];
        g_v[i] = t;
    }
}

// ---------------------------------------------------------------------------
// u[b][m] += sum_{k in chunk} v[k] * X[b][k][m]   (g_u zeroed by k_prep_wb)
// ---------------------------------------------------------------------------
__global__ __launch_bounds__(256)
void k_u(const float* __restrict__ X)
{
    __shared__ float vs[64];
    const int kc = blockIdx.y;
    if (threadIdx.x < 64) vs[threadIdx.x] = g_v[kc * 64 + threadIdx.x];
    __syncthreads();
    const int g = blockIdx.x * 256 + threadIdx.x;
    const int b = g >> 10, m = g & 1023;
    const float* xp = X + ((size_t)b * Cd + kc * 64) * Nd + m;
    float s = 0.f;
    #pragma unroll 8
    for (int k = 0; k < 64; k++) s += vs[k] * xp[(size_t)k * Nd];
    atomicAdd(&g_u[g], s);
}

// ---------------------------------------------------------------------------
// prep WT: transpose + split Wphi, Wtheta
// ---------------------------------------------------------------------------
__global__ __launch_bounds__(256)
void k_prep_wt(const float* __restrict__ Wp, const float* __restrict__ Wt)
{
    __shared__ float t[32][33];
    const float* W = (blockIdx.z == 0) ? Wp : Wt;
    const int r0 = blockIdx.x * 32, q0 = blockIdx.y * 32;
    const int tx = threadIdx.x, ty = threadIdx.y;
    #pragma unroll
    for (int r = 0; r < 4; r++)
        t[ty + 8 * r][tx] = W[(size_t)(q0 + ty + 8 * r) * Cd + r0 + tx];
    __syncthreads();
    #pragma unroll
    for (int r = 0; r < 4; r++) {
        float v = t[tx][ty + 8 * r];
        size_t o = ((size_t)blockIdx.z * Cd + r0 + ty + 8 * r) * Cd + q0 + tx;
        split_bf16(v, g_WT_hi[o], g_WT_lo[o]);
    }
}

// ---------------------------------------------------------------------------
// prep Wb: row-major split + beta bias copy + zero g_u
// ---------------------------------------------------------------------------
__global__ __launch_bounds__(256)
void k_prep_wb(const float* __restrict__ Wb, const float* __restrict__ bb)
{
    int i = blockIdx.x * 256 + threadIdx.x;
    split_bf16(Wb[i], g_Wb_hi[i], g_Wb_lo[i]);
    if (i < Cd) g_bias_b[i] = bb[i];
    if (i < Bd * Nd) g_u[i] = 0.f;
}

// ---------------------------------------------------------------------------
// prep X: transpose + split: XT[b][n][c] = X[b][c][n]
// ---------------------------------------------------------------------------
__global__ __launch_bounds__(256)
void k_prep_x(const float* __restrict__ X)
{
    __shared__ float t[32][33];
    const int b = blockIdx.z, n0 = blockIdx.x * 32, c0 = blockIdx.y * 32;
    const int tx = threadIdx.x, ty = threadIdx.y;
    #pragma unroll
    for (int r = 0; r < 4; r++)
        t[ty + 8 * r][tx] = X[((size_t)b * Cd + c0 + ty + 8 * r) * Nd + n0 + tx];
    __syncthreads();
    #pragma unroll
    for (int r = 0; r < 4; r++) {
        float v = t[tx][ty + 8 * r];
        size_t o = ((size_t)b * Nd + n0 + ty + 8 * r) * Cd + c0 + tx;
        split_bf16(v, g_XT_hi[o], g_XT_lo[o]);
    }
}

// ---------------------------------------------------------------------------
// reduce split-K partials of M and split to bf16 hi/lo
// ---------------------------------------------------------------------------
__global__ __launch_bounds__(256)
void k_redM()
{
    const int i = blockIdx.x * 256 + threadIdx.x;   // < Cd*Cd
    constexpr int CC = Cd * Cd;
    float s = (g_Mpart[i] + g_Mpart[i + CC]) + (g_Mpart[i + 2 * CC] + g_Mpart[i + 3 * CC]);
    split_bf16(s, g_M_hi[i], g_M_lo[i]);
}

// ---------------------------------------------------------------------------
// combine per-coltile softmax partials -> rmax, rinv (one thread per row)
// ---------------------------------------------------------------------------
__global__ __launch_bounds__(256)
void k_comb()
{
    const int r = blockIdx.x * 256 + threadIdx.x;   // < Bd*Nd
    float pm[8], psv[8];
    #pragma unroll
    for (int t = 0; t < 8; t++) {
        pm[t]  = g_pmax[(size_t)r * 8 + t];
        psv[t] = g_psum[(size_t)r * 8 + t];
    }
    float mb = pm[0];
    #pragma unroll
    for (int t = 1; t < 8; t++) mb = fmaxf(mb, pm[t]);
    float s = 0.f;
    #pragma unroll
    for (int t = 0; t < 8; t++) s += psv[t] * __expf(pm[t] - mb);
    g_rmax[r] = mb;
    g_rinv[r] = 1.0f / s;
}

// ---------------------------------------------------------------------------
// trS: AT[b][m][n] = split( exp(S[b][n][m] + u[m] - rmax[n]) * rinv[n] )
// ---------------------------------------------------------------------------
__global__ __launch_bounds__(256)
void k_trS()
{
    __shared__ float t[32][33];
    __shared__ float rm[32], ri[32], uu[32];
    const int b = blockIdx.z, m0 = blockIdx.x * 32, n0 = blockIdx.y * 32;
    const int tx = threadIdx.x, ty = threadIdx.y;
    #pragma unroll
    for (int r = 0; r < 4; r++)
        t[ty + 8 * r][tx] = g_S[((size_t)b * Nd + n0 + ty + 8 * r) * Nd + m0 + tx];
    if (ty == 0) {
        rm[tx] = g_rmax[b * Nd + n0 + tx];
        ri[tx] = g_rinv[b * Nd + n0 + tx];
        uu[tx] = g_u[b * Nd + m0 + tx];
    }
    __syncthreads();
    #pragma unroll
    for (int r = 0; r < 4; r++) {
        const int mj = ty + 8 * r;
        float e = __expf(t[tx][mj] + uu[mj] - rm[tx]) * ri[tx];
        size_t o = ((size_t)b * Nd + m0 + mj) * Nd + n0 + tx;
        split_bf16(e, g_AT_hi[o], g_AT_lo[o]);
    }
}

// ---------------------------------------------------------------------------
// mma.sync GEMM: 256 threads, 8 warps (2x4), warp tile 64x32, CTA 128x128.
// BK=32, 3-stage cp.async pipeline (wait_group 1), swizzled 64B rows, 2 CTA/SM.
// MODE 0: M split-K  D[c][k] += WphiT . WthetaT (K chunk bz) -> g_Mpart fp32
// MODE 1: fused:  flat<32: TT = XT.M ; flat>=32: beta = Wb.XT (+bias)
// MODE 2: G       D[n][m] = XT . TT   -> g_S fp32 + partial softmax stats
// MODE 3: z       D[c][m] = beta . AT (+X)                  -> out fp32
// ---------------------------------------------------------------------------
template <int MODE>
__global__ __launch_bounds__(256, 2)
void k_gemm(const float* __restrict__ Xres, float* __restrict__ Out)
{
    extern __shared__ __align__(1024) char smem[];
    const uint32_t sbase = smem_u32(smem);
    const int tid = threadIdx.x;
    const int lane = tid & 31, wid = tid >> 5;
    const int wr = wid >> 2, wc = wid & 3;          // 2x4 warp grid
    const int bz = blockIdx.z;

    int m0, n0;
    bool isTT = true;
    if (MODE == 1) {
        const int flat = blockIdx.y * 8 + blockIdx.x;   // 0..63
        isTT = flat < 32;
        if (isTT) { m0 = (flat >> 2) * 128; n0 = (flat & 3) * 128; }
        else      { const int f2 = flat - 32; m0 = (f2 >> 3) * 128; n0 = (f2 & 7) * 128; }
    } else {
        m0 = blockIdx.y * 128; n0 = blockIdx.x * 128;
    }

    const __nv_bfloat16 *Ah, *Al, *Bh, *Bl;
    int ldA, ldB;
    constexpr int K = (MODE == 3) ? Nd : ((MODE == 0) ? 128 : Cd);
    const int kbase = (MODE == 0) ? bz * 128 : 0;
    if (MODE == 0) {
        Ah = g_WT_hi;               Al = g_WT_lo;
        Bh = g_WT_hi + Cd * Cd;     Bl = g_WT_lo + Cd * Cd;
        ldA = Cd; ldB = Cd;
    } else if (MODE == 1) {
        if (isTT) {
            Ah = g_XT_hi + (size_t)bz * Nd * Cd;  Al = g_XT_lo + (size_t)bz * Nd * Cd;
            Bh = g_M_hi;                          Bl = g_M_lo;
        } else {
            Ah = g_Wb_hi;                         Al = g_Wb_lo;
            Bh = g_XT_hi + (size_t)bz * Nd * Cd;  Bl = g_XT_lo + (size_t)bz * Nd * Cd;
        }
        ldA = Cd; ldB = Cd;
    } else if (MODE == 2) {
        Ah = g_XT_hi + (size_t)bz * Nd * Cd;  Al = g_XT_lo + (size_t)bz * Nd * Cd;
        Bh = g_TT_hi + (size_t)bz * Nd * Cd;  Bl = g_TT_lo + (size_t)bz * Nd * Cd;
        ldA = Cd; ldB = Cd;
    } else {
        Ah = g_beta_hi + (size_t)bz * Cd * Nd;  Al = g_beta_lo + (size_t)bz * Cd * Nd;
        Bh = g_AT_hi + (size_t)bz * Nd * Nd;    Bl = g_AT_lo + (size_t)bz * Nd * Nd;
        ldA = Nd; ldB = Nd;
    }

    // loader role: quarter oh -> one operand-half; 8 cp.async per k-tile
    const int oh = tid >> 6, lt = tid & 63;
    const __nv_bfloat16* src;
    int row0, ld;
    if      (oh == 0) { src = Ah; row0 = m0; ld = ldA; }
    else if (oh == 1) { src = Al; row0 = m0; ld = ldA; }
    else if (oh == 2) { src = Bh; row0 = n0; ld = ldB; }
    else              { src = Bl; row0 = n0; ld = ldB; }

    auto cp_tile = [&](int buf, int k0) {
        const uint32_t sb = sbase + buf * BUF_B + oh * TILE_B;
        #pragma unroll
        for (int i = 0; i < 8; i++) {
            const int j = i * 64 + lt;
            const int row = j >> 2, c = j & 3;
            cp16(sb + swz(row * ROWB + c * 16),
                 src + (size_t)(row0 + row) * ld + k0 + c * 8);
        }
        cp_commit();
    };

    float acc[4][4][4];
    #pragma unroll
    for (int i = 0; i < 4; i++)
        #pragma unroll
        for (int j = 0; j < 4; j++)
            #pragma unroll
            for (int q = 0; q < 4; q++) acc[i][j][q] = 0.f;

    // ldmatrix lane address components
    const int a_r = lane & 15, a_c = lane >> 4;
    const int b_r = (lane & 7) + ((lane & 16) >> 1);
    const int b_c = (lane >> 3) & 1;

    // prologue: 2 stages in flight
    cp_tile(0, kbase);
    cp_tile(1, kbase + 32);

    constexpr int NT = K / 32;
    int buf = 0;
    for (int t = 0; t < NT; t++) {
        cp_wait1();                 // tile t complete (<=1 group pending)
        __syncthreads();
        if (t + 2 < NT) cp_tile((buf + 2) % 3, kbase + (t + 2) * 32);
        else            cp_commit();   // keep group-count invariant

        const uint32_t sAh = sbase + buf * BUF_B;
        const uint32_t sAl = sAh + TILE_B;
        const uint32_t sBh = sAh + 2 * TILE_B;
        const uint32_t sBl = sAh + 3 * TILE_B;

        #pragma unroll
        for (int ks = 0; ks < 2; ks++) {
            uint32_t bhi[4][2], blo[4][2];
            #pragma unroll
            for (int p = 0; p < 2; p++) {
                const uint32_t off = swz((uint32_t)(wc * 32 + p * 16 + b_r) * ROWB
                                         + (uint32_t)(ks * 2 + b_c) * 16);
                uint32_t th[4], tl[4];
                ldm_x4(th, sBh + off);
                ldm_x4(tl, sBl + off);
                bhi[2 * p][0] = th[0]; bhi[2 * p][1] = th[1];
                bhi[2 * p + 1][0] = th[2]; bhi[2 * p + 1][1] = th[3];
                blo[2 * p][0] = tl[0]; blo[2 * p][1] = tl[1];
                blo[2 * p + 1][0] = tl[2]; blo[2 * p + 1][1] = tl[3];
            }
            #pragma unroll
            for (int mt = 0; mt < 4; mt++) {
                uint32_t ahi[4], alo[4];
                const uint32_t off = swz((uint32_t)(wr * 64 + mt * 16 + a_r) * ROWB
                                         + (uint32_t)(ks * 2 + a_c) * 16);
                ldm_x4(ahi, sAh + off);
                ldm_x4(alo, sAl + off);
                #pragma unroll
                for (int nt = 0; nt < 4; nt++) {
                    mma_bf16(acc[mt][nt], ahi, bhi[nt][0], bhi[nt][1]);
                    mma_bf16(acc[mt][nt], ahi, blo[nt][0], blo[nt][1]);
                    mma_bf16(acc[mt][nt], alo, bhi[nt][0], bhi[nt][1]);
                }
            }
        }
        buf = (buf + 1) % 3;
    }

    // epilogue: fragment lane -> (row = lane>>2 [+8], cols (lane&3)*2, +1)
    #pragma unroll
    for (int mt = 0; mt < 4; mt++)
        #pragma unroll
        for (int nt = 0; nt < 4; nt++) {
            const int row = m0 + wr * 64 + mt * 16 + (lane >> 2);
            const int col = n0 + wc * 32 + nt * 8 + (lane & 3) * 2;
            const float* d = acc[mt][nt];

            if (MODE == 0) {
                float* Mp = g_Mpart + (size_t)bz * Cd * Cd;
                const size_t o0 = (size_t)row * Cd + col;
                *reinterpret_cast<float2*>(Mp + o0) = make_float2(d[0], d[1]);
                *reinterpret_cast<float2*>(Mp + o0 + 8 * Cd) = make_float2(d[2], d[3]);
            } else if (MODE == 1) {
                float q0 = d[0], q1 = d[1], q2 = d[2], q3 = d[3];
                __nv_bfloat16 *dh, *dl;
                size_t o0;
                int ldo;
                if (isTT) {
                    ldo = Cd; o0 = ((size_t)bz * Nd + row) * ldo + col;
                    dh = g_TT_hi; dl = g_TT_lo;
                } else {
                    q0 += g_bias_b[row];     q1 += g_bias_b[row];
                    q2 += g_bias_b[row + 8]; q3 += g_bias_b[row + 8];
                    ldo = Nd; o0 = ((size_t)bz * Cd + row) * ldo + col;
                    dh = g_beta_hi; dl = g_beta_lo;
                }
                __nv_bfloat16 h0, l0, h1, l1, h2, l2, h3, l3;
                split_bf16(q0, h0, l0); split_bf16(q1, h1, l1);
                split_bf16(q2, h2, l2); split_bf16(q3, h3, l3);
                const size_t o1 = o0 + 8 * (size_t)ldo;
                *reinterpret_cast<uint32_t*>(dh + o0) =
                    (uint32_t)__bfloat16_as_ushort(h0) | ((uint32_t)__bfloat16_as_ushort(h1) << 16);
                *reinterpret_cast<uint32_t*>(dl + o0) =
                    (uint32_t)__bfloat16_as_ushort(l0) | ((uint32_t)__bfloat16_as_ushort(l1) << 16);
                *reinterpret_cast<uint32_t*>(dh + o1) =
                    (uint32_t)__bfloat16_as_ushort(h2) | ((uint32_t)__bfloat16_as_ushort(h3) << 16);
                *reinterpret_cast<uint32_t*>(dl + o1) =
                    (uint32_t)__bfloat16_as_ushort(l2) | ((uint32_t)__bfloat16_as_ushort(l3) << 16);
            } else if (MODE == 2) {
                const size_t o0 = ((size_t)bz * Nd + row) * Nd + col;
                *reinterpret_cast<float2*>(g_S + o0) = make_float2(d[0], d[1]);
                *reinterpret_cast<float2*>(g_S + o0 + 8 * Nd) = make_float2(d[2], d[3]);
            } else {
                const size_t o0 = ((size_t)bz * Cd + row) * Nd + col;
                const size_t o1 = o0 + 8 * Nd;
                float2 x0 = *reinterpret_cast<const float2*>(Xres + o0);
                float2 x1 = *reinterpret_cast<const float2*>(Xres + o1);
                *reinterpret_cast<float2*>(Out + o0) = make_float2(d[0] + x0.x, d[1] + x0.y);
                *reinterpret_cast<float2*>(Out + o1) = make_float2(d[2] + x1.x, d[3] + x1.y);
            }
        }

    // MODE 2: fused partial softmax stats over this CTA's 128-col tile.
    // Values = acc + u[col]; per-row (max, expsum) across the 128 cols.
    if (MODE == 2) {
        __syncthreads();                              // pipeline smem now free
        float* pm = reinterpret_cast<float*>(smem);   // [4][128]
        float* ps = pm + 512;                          // [4][128]

        #pragma unroll
        for (int mt = 0; mt < 4; mt++) {
            float vs[4][4];
            float mx0 = -1e30f, mx1 = -1e30f;
            #pragma unroll
            for (int nt = 0; nt < 4; nt++) {
                const int col = n0 + wc * 32 + nt * 8 + (lane & 3) * 2;
                const float u0 = g_u[bz * Nd + col];
                const float u1 = g_u[bz * Nd + col + 1];
                const float* d = acc[mt][nt];
                vs[nt][0] = d[0] + u0; vs[nt][1] = d[1] + u1;
                vs[nt][2] = d[2] + u0; vs[nt][3] = d[3] + u1;
                mx0 = fmaxf(mx0, fmaxf(vs[nt][0], vs[nt][1]));
                mx1 = fmaxf(mx1, fmaxf(vs[nt][2], vs[nt][3]));
            }
            mx0 = fmaxf(mx0, __shfl_xor_sync(0xffffffffu, mx0, 1));
            mx0 = fmaxf(mx0, __shfl_xor_sync(0xffffffffu, mx0, 2));
            mx1 = fmaxf(mx1, __shfl_xor_sync(0xffffffffu, mx1, 1));
            mx1 = fmaxf(mx1, __shfl_xor_sync(0xffffffffu, mx1, 2));
            float s0 = 0.f, s1 = 0.f;
            #pragma unroll
            for (int nt = 0; nt < 4; nt++) {
                s0 += __expf(vs[nt][0] - mx0) + __expf(vs[nt][1] - mx0);
                s1 += __expf(vs[nt][2] - mx1) + __expf(vs[nt][3] - mx1);
            }
            s0 += __shfl_xor_sync(0xffffffffu, s0, 1);
            s0 += __shfl_xor_sync(0xffffffffu, s0, 2);
            s1 += __shfl_xor_sync(0xffffffffu, s1, 1);
            s1 += __shfl_xor_sync(0xffffffffu, s1, 2);
            if ((lane & 3) == 0) {
                const int rl = wr * 64 + mt * 16 + (lane >> 2);
                pm[wc * 128 + rl]     = mx0;  ps[wc * 128 + rl]     = s0;
                pm[wc * 128 + rl + 8] = mx1;  ps[wc * 128 + rl + 8] = s1;
            }
        }
        __syncthreads();
        if (tid < 128) {
            float mb = pm[tid];
            #pragma unroll
            for (int w = 1; w < 4; w++) mb = fmaxf(mb, pm[w * 128 + tid]);
            float sb = 0.f;
            #pragma unroll
            for (int w = 0; w < 4; w++)
                sb += ps[w * 128 + tid] * __expf(pm[w * 128 + tid] - mb);
            const size_t o = ((size_t)bz * Nd + m0 + tid) * 8 + (n0 >> 7);
            g_pmax[o] = mb;
            g_psum[o] = sb;
        }
    }
}

// ---------------------------------------------------------------------------
extern "C" void kernel_launch(void* const* d_in, const int* in_sizes, int n_in,
                              void* d_out, int out_size)
{
    (void)in_sizes; (void)n_in; (void)out_size;
    const float* X  = (const float*)d_in[0];
    const float* Wp = (const float*)d_in[1];
    const float* bp = (const float*)d_in[2];
    const float* Wt = (const float*)d_in[3];
    const float* bt = (const float*)d_in[4];
    const float* Wb = (const float*)d_in[5];
    const float* bb = (const float*)d_in[6];
    float* out = (float*)d_out;
    (void)bt;

    static bool attr_done = false;
    if (!attr_done) {
        cudaFuncSetAttribute(k_gemm<0>, cudaFuncAttributeMaxDynamicSharedMemorySize, SM_TOTAL);
        cudaFuncSetAttribute(k_gemm<1>, cudaFuncAttributeMaxDynamicSharedMemorySize, SM_TOTAL);
        cudaFuncSetAttribute(k_gemm<2>, cudaFuncAttributeMaxDynamicSharedMemorySize, SM_TOTAL);
        cudaFuncSetAttribute(k_gemm<3>, cudaFuncAttributeMaxDynamicSharedMemorySize, SM_TOTAL);
        attr_done = true;
    }

    k_prep_wb<<<(Cd * Cd) / 256, 256>>>(Wb, bb);                     // + zero g_u
    k_v      <<<16, 256>>>(Wt, bp);
    k_prep_wt<<<dim3(16, 16, 2), dim3(32, 8)>>>(Wp, Wt);
    k_prep_x <<<dim3(Nd / 32, Cd / 32, Bd), dim3(32, 8)>>>(X);
    k_u      <<<dim3(32, 8), 256>>>(X);
    k_gemm<0><<<dim3(4, 4, 4), 256, SM_TOTAL>>>(nullptr, nullptr);   // M split-K
    k_redM   <<<(Cd * Cd) / 256, 256>>>();
    k_gemm<1><<<dim3(8, 8, Bd), 256, SM_TOTAL>>>(nullptr, nullptr);  // TT + beta fused
    k_gemm<2><<<dim3(8, 8, Bd), 256, SM_TOTAL>>>(nullptr, nullptr);  // G + stats
    k_comb   <<<(Bd * Nd) / 256, 256>>>();
    k_trS    <<<dim3(Nd / 32, Nd / 32, Bd), dim3(32, 8)>>>();
    k_gemm<3><<<dim3(8, 4, Bd), 256, SM_TOTAL>>>(X, out);            // z -> out
}

// round 15
// speedup vs baseline: 1.3432x; 1.0392x over previous
#include <cuda_runtime.h>
#include <cuda_bf16.h>
#include <cstdint>

// ---------------------------------------------------------------------------
// Non-local attention block, B=8, C=512, N=1024 (H=W=32), fp32 in/out.
// R14: R13 engine (BK=32, swizzled 64B rows, 3-stage cp.async, 2 CTAs/SM)
//      + u fused into prep_x (k_u dropped) + G writes S transposed so the
//      exp/split pass is a pure streaming kernel + launch order puts the
//      TT/beta GEMM at ncu's captured slot (6th launch).
// ---------------------------------------------------------------------------

namespace {
constexpr int Cd = 512, Nd = 1024, Bd = 8;
constexpr int ROWB   = 64;                 // 32 bf16 = 64B data, swizzled
constexpr int TILE_B = 128 * ROWB;         // 8192 B per operand-half tile
constexpr int BUF_B  = 4 * TILE_B;         // Ahi,Alo,Bhi,Blo = 32768 per stage
constexpr int STAGES = 3;
constexpr int SM_TOTAL = STAGES * BUF_B;   // 98304 -> 2 CTAs/SM
}

__device__ __forceinline__ uint32_t swz(uint32_t off) {
    return off ^ ((off >> 3) & 0x70);      // Swizzle<3,4,3> on 64B rows
}

// ---- device scratch --------------------------------------------------------
__device__ __nv_bfloat16 g_XT_hi[Bd * Nd * Cd];    // [b][n][c]
__device__ __nv_bfloat16 g_XT_lo[Bd * Nd * Cd];
__device__ __nv_bfloat16 g_WT_hi[2 * Cd * Cd];     // rows 0-511 WphiT, 512-1023 WthetaT
__device__ __nv_bfloat16 g_WT_lo[2 * Cd * Cd];
__device__ __nv_bfloat16 g_Wb_hi[Cd * Cd];         // Wbeta row-major [c][k]
__device__ __nv_bfloat16 g_Wb_lo[Cd * Cd];
__device__ float         g_bias_b[Cd];
__device__ float         g_v[Cd];                  // Wtheta^T bphi
__device__ float         g_u[Bd * Nd];             // v^T X_b
__device__ float         g_rmax[Bd * Nd];          // row max of S_eff
__device__ float         g_rinv[Bd * Nd];          // 1 / row sum exp
__device__ float         g_Mpart[4 * Cd * Cd];     // split-K partials for M
__device__ __nv_bfloat16 g_M_hi[Cd * Cd];          // [c][k]
__device__ __nv_bfloat16 g_M_lo[Cd * Cd];
__device__ __nv_bfloat16 g_TT_hi[Bd * Nd * Cd];    // [b][m][c]
__device__ __nv_bfloat16 g_TT_lo[Bd * Nd * Cd];
__device__ __nv_bfloat16 g_beta_hi[Bd * Cd * Nd];  // [b][c][n]
__device__ __nv_bfloat16 g_beta_lo[Bd * Cd * Nd];
__device__ float         g_S[Bd * Nd * Nd];        // ST: [b][m][n] (S transposed, no u)
__device__ float         g_pmax[Bd * Nd * 8];      // per-row per-coltile max
__device__ float         g_psum[Bd * Nd * 8];      // per-row per-coltile expsum
__device__ __nv_bfloat16 g_AT_hi[Bd * Nd * Nd];    // [b][m][n]
__device__ __nv_bfloat16 g_AT_lo[Bd * Nd * Nd];

// ---- helpers ---------------------------------------------------------------
__device__ __forceinline__ uint32_t smem_u32(const void* p) {
    uint32_t a;
    asm("{ .reg .u64 t; cvta.to.shared.u64 t, %1; cvt.u32.u64 %0, t; }"
        : "=r"(a) : "l"(p));
    return a;
}
__device__ __forceinline__ void cp16(uint32_t dst, const void* src) {
    asm volatile("cp.async.cg.shared.global [%0], [%1], 16;"
                 :: "r"(dst), "l"(__cvta_generic_to_global(src)) : "memory");
}
__device__ __forceinline__ void cp_commit() {
    asm volatile("cp.async.commit_group;" ::: "memory");
}
__device__ __forceinline__ void cp_wait1() {
    asm volatile("cp.async.wait_group 1;" ::: "memory");
}
__device__ __forceinline__ void ldm_x4(uint32_t (&r)[4], uint32_t addr) {
    asm volatile("ldmatrix.sync.aligned.m8n8.x4.shared.b16 {%0,%1,%2,%3}, [%4];"
        : "=r"(r[0]), "=r"(r[1]), "=r"(r[2]), "=r"(r[3]) : "r"(addr));
}
__device__ __forceinline__ void mma_bf16(float (&d)[4], const uint32_t (&a)[4],
                                         const uint32_t b0, const uint32_t b1) {
    asm volatile(
        "mma.sync.aligned.m16n8k16.row.col.f32.bf16.bf16.f32 "
        "{%0,%1,%2,%3},{%4,%5,%6,%7},{%8,%9},{%0,%1,%2,%3};"
        : "+f"(d[0]), "+f"(d[1]), "+f"(d[2]), "+f"(d[3])
        : "r"(a[0]), "r"(a[1]), "r"(a[2]), "r"(a[3]), "r"(b0), "r"(b1));
}
__device__ __forceinline__ void split_bf16(float v, __nv_bfloat16& h, __nv_bfloat16& l) {
    h = __float2bfloat16(v);
    l = __float2bfloat16(v - __bfloat162float(h));
}

// ---------------------------------------------------------------------------
// prep W (merged): z<2 -> transpose+split Wphi/Wtheta; z==2 -> split Wb + bias
// grid (16, 16, 3), block 256 (as (32,8) for z<2; flat for z==2)
// ---------------------------------------------------------------------------
__global__ __launch_bounds__(256)
void k_prep_w(const float* __restrict__ Wp, const float* __restrict__ Wt,
              const float* __restrict__ Wb, const float* __restrict__ bb)
{
    if (blockIdx.z < 2) {
        __shared__ float t[32][33];
        const float* W = (blockIdx.z == 0) ? Wp : Wt;
        const int r0 = blockIdx.x * 32, q0 = blockIdx.y * 32;
        const int tx = threadIdx.x & 31, ty = threadIdx.x >> 5;
        #pragma unroll
        for (int r = 0; r < 4; r++)
            t[ty + 8 * r][tx] = W[(size_t)(q0 + ty + 8 * r) * Cd + r0 + tx];
        __syncthreads();
        #pragma unroll
        for (int r = 0; r < 4; r++) {
            float v = t[tx][ty + 8 * r];
            size_t o = ((size_t)blockIdx.z * Cd + r0 + ty + 8 * r) * Cd + q0 + tx;
            split_bf16(v, g_WT_hi[o], g_WT_lo[o]);
        }
    } else {
        const int base = ((blockIdx.y * 16 + blockIdx.x) * 256 + threadIdx.x) * 4;
        #pragma unroll
        for (int j = 0; j < 4; j++) {
            const int i = base + j;
            split_bf16(Wb[i], g_Wb_hi[i], g_Wb_lo[i]);
            if (i < Cd) g_bias_b[i] = bb[i];
        }
    }
}

// ---------------------------------------------------------------------------
// v[i] = sum_q Wt[q][i] * bphi[q]  (atomic-free) + zero g_u
// ---------------------------------------------------------------------------
__global__ __launch_bounds__(256)
void k_v(const float* __restrict__ Wt, const float* __restrict__ bphi)
{
    __shared__ float part[8][32];
    const int gt = blockIdx.x * 256 + threadIdx.x;   // < 4096
    g_u[2 * gt]     = 0.f;
    g_u[2 * gt + 1] = 0.f;

    const int i  = blockIdx.x * 32 + (threadIdx.x & 31);
    const int qs = threadIdx.x >> 5;
    float s = 0.f;
    #pragma unroll 8
    for (int r = 0; r < 64; r++) {
        const int q = qs * 64 + r;
        s += Wt[(size_t)q * Cd + i] * bphi[q];
    }
    part[qs][threadIdx.x & 31] = s;
    __syncthreads();
    if (qs == 0) {
        float t = part[0][threadIdx.x];
        #pragma unroll
        for (int w = 1; w < 8; w++) t += part[w][threadIdx.x];
        g_v[i] = t;
    }
}

// ---------------------------------------------------------------------------
// prep X: transpose + split XT[b][n][c] = X[b][c][n], and accumulate
// u[b][n] += sum_{c in tile} v[c] * X[b][c][n]  (atomicAdd per (block, n))
// ---------------------------------------------------------------------------
__global__ __launch_bounds__(256)
void k_prep_x(const float* __restrict__ X)
{
    __shared__ float t[32][33];
    const int b = blockIdx.z, n0 = blockIdx.x * 32, c0 = blockIdx.y * 32;
    const int tx = threadIdx.x & 31, ty = threadIdx.x >> 5;
    #pragma unroll
    for (int r = 0; r < 4; r++)
        t[ty + 8 * r][tx] = X[((size_t)b * Cd + c0 + ty + 8 * r) * Nd + n0 + tx];
    __syncthreads();

    float up = 0.f;
    #pragma unroll
    for (int r = 0; r < 4; r++) {
        const int cc = ty + 8 * r;
        float v = t[cc][tx];             // X[c0+cc][n0+tx]
        up += g_v[c0 + cc] * v;
        // transposed split-store
        float vt = t[tx][cc];            // X[c0+tx][n0+cc]... careful: see below
        (void)vt;
    }
    // split-store (transposed) — separate loop reading t[tx][*]
    #pragma unroll
    for (int r = 0; r < 4; r++) {
        float v = t[tx][ty + 8 * r];
        size_t o = ((size_t)b * Nd + n0 + ty + 8 * r) * Cd + c0 + tx;
        split_bf16(v, g_XT_hi[o], g_XT_lo[o]);
    }
    __syncthreads();
    t[ty][tx] = up;                      // partial per (n'=tx, c-group=ty)
    __syncthreads();
    if (ty == 0) {
        float s = t[0][tx];
        #pragma unroll
        for (int w = 1; w < 8; w++) s += t[w][tx];
        atomicAdd(&g_u[b * Nd + n0 + tx], s);
    }
}

// ---------------------------------------------------------------------------
// reduce split-K partials of M and split to bf16 hi/lo
// ---------------------------------------------------------------------------
__global__ __launch_bounds__(256)
void k_redM()
{
    const int i = blockIdx.x * 256 + threadIdx.x;   // < Cd*Cd
    constexpr int CC = Cd * Cd;
    float s = (g_Mpart[i] + g_Mpart[i + CC]) + (g_Mpart[i + 2 * CC] + g_Mpart[i + 3 * CC]);
    split_bf16(s, g_M_hi[i], g_M_lo[i]);
}

// ---------------------------------------------------------------------------
// combine per-coltile softmax partials -> rmax, rinv (one thread per row)
// ---------------------------------------------------------------------------
__global__ __launch_bounds__(256)
void k_comb()
{
    const int r = blockIdx.x * 256 + threadIdx.x;   // < Bd*Nd
    float pm[8], psv[8];
    #pragma unroll
    for (int t = 0; t < 8; t++) {
        pm[t]  = g_pmax[(size_t)r * 8 + t];
        psv[t] = g_psum[(size_t)r * 8 + t];
    }
    float mb = pm[0];
    #pragma unroll
    for (int t = 1; t < 8; t++) mb = fmaxf(mb, pm[t]);
    float s = 0.f;
    #pragma unroll
    for (int t = 0; t < 8; t++) s += psv[t] * __expf(pm[t] - mb);
    g_rmax[r] = mb;
    g_rinv[r] = 1.0f / s;
}

// ---------------------------------------------------------------------------
// exps (streaming): AT[b][m][n] = split( exp(ST[b][m][n] + u[m] - rmax[n]) * rinv[n] )
// one thread = 4 consecutive n of one m row; fully coalesced.
// ---------------------------------------------------------------------------
__global__ __launch_bounds__(256)
void k_exps()
{
    const int flat = blockIdx.x * 256 + threadIdx.x;    // < Bd*Nd*256
    const int n4 = flat & 255;                          // 256 groups of 4 n
    const int mg = flat >> 8;                           // global m row (b*Nd+m)
    const int b  = mg >> 10;
    const size_t o = ((size_t)mg) * Nd + n4 * 4;

    float4 st = *reinterpret_cast<const float4*>(g_S + o);
    const int nb = b * Nd + n4 * 4;
    float4 rm = *reinterpret_cast<const float4*>(g_rmax + nb);
    float4 ri = *reinterpret_cast<const float4*>(g_rinv + nb);
    const float um = g_u[mg];

    float e0 = __expf(st.x + um - rm.x) * ri.x;
    float e1 = __expf(st.y + um - rm.y) * ri.y;
    float e2 = __expf(st.z + um - rm.z) * ri.z;
    float e3 = __expf(st.w + um - rm.w) * ri.w;

    __nv_bfloat16 h0, l0, h1, l1, h2, l2, h3, l3;
    split_bf16(e0, h0, l0); split_bf16(e1, h1, l1);
    split_bf16(e2, h2, l2); split_bf16(e3, h3, l3);
    uint2 ph = make_uint2(
        (uint32_t)__bfloat16_as_ushort(h0) | ((uint32_t)__bfloat16_as_ushort(h1) << 16),
        (uint32_t)__bfloat16_as_ushort(h2) | ((uint32_t)__bfloat16_as_ushort(h3) << 16));
    uint2 pl = make_uint2(
        (uint32_t)__bfloat16_as_ushort(l0) | ((uint32_t)__bfloat16_as_ushort(l1) << 16),
        (uint32_t)__bfloat16_as_ushort(l2) | ((uint32_t)__bfloat16_as_ushort(l3) << 16));
    *reinterpret_cast<uint2*>(g_AT_hi + o) = ph;
    *reinterpret_cast<uint2*>(g_AT_lo + o) = pl;
}

// ---------------------------------------------------------------------------
// mma.sync GEMM: 256 threads, 8 warps (2x4), warp tile 64x32, CTA 128x128.
// BK=32, 3-stage cp.async pipeline (wait_group 1), swizzled 64B rows, 2 CTA/SM.
// MODE 0: M split-K  D[c][k] += WphiT . WthetaT (K chunk bz) -> g_Mpart fp32
// MODE 1: fused:  flat<32: TT = XT.M ; flat>=32: beta = Wb.XT (+bias)
// MODE 2: G  D[n][m] = XT . TT -> ST (transposed store) + partial softmax stats
// MODE 3: z  D[c][m] = beta . AT (+X)                   -> out fp32
// ---------------------------------------------------------------------------
template <int MODE>
__global__ __launch_bounds__(256, 2)
void k_gemm(const float* __restrict__ Xres, float* __restrict__ Out)
{
    extern __shared__ __align__(1024) char smem[];
    const uint32_t sbase = smem_u32(smem);
    const int tid = threadIdx.x;
    const int lane = tid & 31, wid = tid >> 5;
    const int wr = wid >> 2, wc = wid & 3;          // 2x4 warp grid
    const int bz = blockIdx.z;

    int m0, n0;
    bool isTT = true;
    if (MODE == 1) {
        const int flat = blockIdx.y * 8 + blockIdx.x;   // 0..63
        isTT = flat < 32;
        if (isTT) { m0 = (flat >> 2) * 128; n0 = (flat & 3) * 128; }
        else      { const int f2 = flat - 32; m0 = (f2 >> 3) * 128; n0 = (f2 & 7) * 128; }
    } else {
        m0 = blockIdx.y * 128; n0 = blockIdx.x * 128;
    }

    const __nv_bfloat16 *Ah, *Al, *Bh, *Bl;
    int ldA, ldB;
    constexpr int K = (MODE == 3) ? Nd : ((MODE == 0) ? 128 : Cd);
    const int kbase = (MODE == 0) ? bz * 128 : 0;
    if (MODE == 0) {
        Ah = g_WT_hi;               Al = g_WT_lo;
        Bh = g_WT_hi + Cd * Cd;     Bl = g_WT_lo + Cd * Cd;
        ldA = Cd; ldB = Cd;
    } else if (MODE == 1) {
        if (isTT) {
            Ah = g_XT_hi + (size_t)bz * Nd * Cd;  Al = g_XT_lo + (size_t)bz * Nd * Cd;
            Bh = g_M_hi;                          Bl = g_M_lo;
        } else {
            Ah = g_Wb_hi;                         Al = g_Wb_lo;
            Bh = g_XT_hi + (size_t)bz * Nd * Cd;  Bl = g_XT_lo + (size_t)bz * Nd * Cd;
        }
        ldA = Cd; ldB = Cd;
    } else if (MODE == 2) {
        Ah = g_XT_hi + (size_t)bz * Nd * Cd;  Al = g_XT_lo + (size_t)bz * Nd * Cd;
        Bh = g_TT_hi + (size_t)bz * Nd * Cd;  Bl = g_TT_lo + (size_t)bz * Nd * Cd;
        ldA = Cd; ldB = Cd;
    } else {
        Ah = g_beta_hi + (size_t)bz * Cd * Nd;  Al = g_beta_lo + (size_t)bz * Cd * Nd;
        Bh = g_AT_hi + (size_t)bz * Nd * Nd;    Bl = g_AT_lo + (size_t)bz * Nd * Nd;
        ldA = Nd; ldB = Nd;
    }

    // loader role: quarter oh -> one operand-half; 8 cp.async per k-tile
    const int oh = tid >> 6, lt = tid & 63;
    const __nv_bfloat16* src;
    int row0, ld;
    if      (oh == 0) { src = Ah; row0 = m0; ld = ldA; }
    else if (oh == 1) { src = Al; row0 = m0; ld = ldA; }
    else if (oh == 2) { src = Bh; row0 = n0; ld = ldB; }
    else              { src = Bl; row0 = n0; ld = ldB; }

    auto cp_tile = [&](int buf, int k0) {
        const uint32_t sb = sbase + buf * BUF_B + oh * TILE_B;
        #pragma unroll
        for (int i = 0; i < 8; i++) {
            const int j = i * 64 + lt;
            const int row = j >> 2, c = j & 3;
            cp16(sb + swz(row * ROWB + c * 16),
                 src + (size_t)(row0 + row) * ld + k0 + c * 8);
        }
        cp_commit();
    };

    float acc[4][4][4];
    #pragma unroll
    for (int i = 0; i < 4; i++)
        #pragma unroll
        for (int j = 0; j < 4; j++)
            #pragma unroll
            for (int q = 0; q < 4; q++) acc[i][j][q] = 0.f;

    // ldmatrix lane address components
    const int a_r = lane & 15, a_c = lane >> 4;
    const int b_r = (lane & 7) + ((lane & 16) >> 1);
    const int b_c = (lane >> 3) & 1;

    // prologue: 2 stages in flight
    cp_tile(0, kbase);
    cp_tile(1, kbase + 32);

    constexpr int NT = K / 32;
    int buf = 0;
    for (int t = 0; t < NT; t++) {
        cp_wait1();                 // tile t complete (<=1 group pending)
        __syncthreads();
        if (t + 2 < NT) cp_tile((buf + 2) % 3, kbase + (t + 2) * 32);
        else            cp_commit();   // keep group-count invariant

        const uint32_t sAh = sbase + buf * BUF_B;
        const uint32_t sAl = sAh + TILE_B;
        const uint32_t sBh = sAh + 2 * TILE_B;
        const uint32_t sBl = sAh + 3 * TILE_B;

        #pragma unroll
        for (int ks = 0; ks < 2; ks++) {
            uint32_t bhi[4][2], blo[4][2];
            #pragma unroll
            for (int p = 0; p < 2; p++) {
                const uint32_t off = swz((uint32_t)(wc * 32 + p * 16 + b_r) * ROWB
                                         + (uint32_t)(ks * 2 + b_c) * 16);
                uint32_t th[4], tl[4];
                ldm_x4(th, sBh + off);
                ldm_x4(tl, sBl + off);
                bhi[2 * p][0] = th[0]; bhi[2 * p][1] = th[1];
                bhi[2 * p + 1][0] = th[2]; bhi[2 * p + 1][1] = th[3];
                blo[2 * p][0] = tl[0]; blo[2 * p][1] = tl[1];
                blo[2 * p + 1][0] = tl[2]; blo[2 * p + 1][1] = tl[3];
            }
            #pragma unroll
            for (int mt = 0; mt < 4; mt++) {
                uint32_t ahi[4], alo[4];
                const uint32_t off = swz((uint32_t)(wr * 64 + mt * 16 + a_r) * ROWB
                                         + (uint32_t)(ks * 2 + a_c) * 16);
                ldm_x4(ahi, sAh + off);
                ldm_x4(alo, sAl + off);
                #pragma unroll
                for (int nt = 0; nt < 4; nt++) {
                    mma_bf16(acc[mt][nt], ahi, bhi[nt][0], bhi[nt][1]);
                    mma_bf16(acc[mt][nt], ahi, blo[nt][0], blo[nt][1]);
                    mma_bf16(acc[mt][nt], alo, bhi[nt][0], bhi[nt][1]);
                }
            }
        }
        buf = (buf + 1) % 3;
    }

    // epilogue: fragment lane -> (row = lane>>2 [+8], cols (lane&3)*2, +1)
    #pragma unroll
    for (int mt = 0; mt < 4; mt++)
        #pragma unroll
        for (int nt = 0; nt < 4; nt++) {
            const int row = m0 + wr * 64 + mt * 16 + (lane >> 2);
            const int col = n0 + wc * 32 + nt * 8 + (lane & 3) * 2;
            const float* d = acc[mt][nt];

            if (MODE == 0) {
                float* Mp = g_Mpart + (size_t)bz * Cd * Cd;
                const size_t o0 = (size_t)row * Cd + col;
                *reinterpret_cast<float2*>(Mp + o0) = make_float2(d[0], d[1]);
                *reinterpret_cast<float2*>(Mp + o0 + 8 * Cd) = make_float2(d[2], d[3]);
            } else if (MODE == 1) {
                float q0 = d[0], q1 = d[1], q2 = d[2], q3 = d[3];
                __nv_bfloat16 *dh, *dl;
                size_t o0;
                int ldo;
                if (isTT) {
                    ldo = Cd; o0 = ((size_t)bz * Nd + row) * ldo + col;
                    dh = g_TT_hi; dl = g_TT_lo;
                } else {
                    q0 += g_bias_b[row];     q1 += g_bias_b[row];
                    q2 += g_bias_b[row + 8]; q3 += g_bias_b[row + 8];
                    ldo = Nd; o0 = ((size_t)bz * Cd + row) * ldo + col;
                    dh = g_beta_hi; dl = g_beta_lo;
                }
                __nv_bfloat16 h0, l0, h1, l1, h2, l2, h3, l3;
                split_bf16(q0, h0, l0); split_bf16(q1, h1, l1);
                split_bf16(q2, h2, l2); split_bf16(q3, h3, l3);
                const size_t o1 = o0 + 8 * (size_t)ldo;
                *reinterpret_cast<uint32_t*>(dh + o0) =
                    (uint32_t)__bfloat16_as_ushort(h0) | ((uint32_t)__bfloat16_as_ushort(h1) << 16);
                *reinterpret_cast<uint32_t*>(dl + o0) =
                    (uint32_t)__bfloat16_as_ushort(l0) | ((uint32_t)__bfloat16_as_ushort(l1) << 16);
                *reinterpret_cast<uint32_t*>(dh + o1) =
                    (uint32_t)__bfloat16_as_ushort(h2) | ((uint32_t)__bfloat16_as_ushort(h3) << 16);
                *reinterpret_cast<uint32_t*>(dl + o1) =
                    (uint32_t)__bfloat16_as_ushort(l2) | ((uint32_t)__bfloat16_as_ushort(l3) << 16);
            } else if (MODE == 2) {
                // transposed store: ST[b][m=col][n=row]
                const size_t o = ((size_t)bz * Nd + col) * Nd + row;
                g_S[o]          = d[0];
                g_S[o + Nd]     = d[1];
                g_S[o + 8]      = d[2];
                g_S[o + Nd + 8] = d[3];
            } else {
                const size_t o0 = ((size_t)bz * Cd + row) * Nd + col;
                const size_t o1 = o0 + 8 * Nd;
                float2 x0 = *reinterpret_cast<const float2*>(Xres + o0);
                float2 x1 = *reinterpret_cast<const float2*>(Xres + o1);
                *reinterpret_cast<float2*>(Out + o0) = make_float2(d[0] + x0.x, d[1] + x0.y);
                *reinterpret_cast<float2*>(Out + o1) = make_float2(d[2] + x1.x, d[3] + x1.y);
            }
        }

    // MODE 2: fused partial softmax stats over this CTA's 128-col tile.
    if (MODE == 2) {
        __syncthreads();                              // pipeline smem now free
        float* pm = reinterpret_cast<float*>(smem);   // [4][128]
        float* ps = pm + 512;                          // [4][128]

        #pragma unroll
        for (int mt = 0; mt < 4; mt++) {
            float vs[4][4];
            float mx0 = -1e30f, mx1 = -1e30f;
            #pragma unroll
            for (int nt = 0; nt < 4; nt++) {
                const int col = n0 + wc * 32 + nt * 8 + (lane & 3) * 2;
                const float u0 = g_u[bz * Nd + col];
                const float u1 = g_u[bz * Nd + col + 1];
                const float* d = acc[mt][nt];
                vs[nt][0] = d[0] + u0; vs[nt][1] = d[1] + u1;
                vs[nt][2] = d[2] + u0; vs[nt][3] = d[3] + u1;
                mx0 = fmaxf(mx0, fmaxf(vs[nt][0], vs[nt][1]));
                mx1 = fmaxf(mx1, fmaxf(vs[nt][2], vs[nt][3]));
            }
            mx0 = fmaxf(mx0, __shfl_xor_sync(0xffffffffu, mx0, 1));
            mx0 = fmaxf(mx0, __shfl_xor_sync(0xffffffffu, mx0, 2));
            mx1 = fmaxf(mx1, __shfl_xor_sync(0xffffffffu, mx1, 1));
            mx1 = fmaxf(mx1, __shfl_xor_sync(0xffffffffu, mx1, 2));
            float s0 = 0.f, s1 = 0.f;
            #pragma unroll
            for (int nt = 0; nt < 4; nt++) {
                s0 += __expf(vs[nt][0] - mx0) + __expf(vs[nt][1] - mx0);
                s1 += __expf(vs[nt][2] - mx1) + __expf(vs[nt][3] - mx1);
            }
            s0 += __shfl_xor_sync(0xffffffffu, s0, 1);
            s0 += __shfl_xor_sync(0xffffffffu, s0, 2);
            s1 += __shfl_xor_sync(0xffffffffu, s1, 1);
            s1 += __shfl_xor_sync(0xffffffffu, s1, 2);
            if ((lane & 3) == 0) {
                const int rl = wr * 64 + mt * 16 + (lane >> 2);
                pm[wc * 128 + rl]     = mx0;  ps[wc * 128 + rl]     = s0;
                pm[wc * 128 + rl + 8] = mx1;  ps[wc * 128 + rl + 8] = s1;
            }
        }
        __syncthreads();
        if (tid < 128) {
            float mb = pm[tid];
            #pragma unroll
            for (int w = 1; w < 4; w++) mb = fmaxf(mb, pm[w * 128 + tid]);
            float sb = 0.f;
            #pragma unroll
            for (int w = 0; w < 4; w++)
                sb += ps[w * 128 + tid] * __expf(pm[w * 128 + tid] - mb);
            const size_t o = ((size_t)bz * Nd + m0 + tid) * 8 + (n0 >> 7);
            g_pmax[o] = mb;
            g_psum[o] = sb;
        }
    }
}

// ---------------------------------------------------------------------------
extern "C" void kernel_launch(void* const* d_in, const int* in_sizes, int n_in,
                              void* d_out, int out_size)
{
    (void)in_sizes; (void)n_in; (void)out_size;
    const float* X  = (const float*)d_in[0];
    const float* Wp = (const float*)d_in[1];
    const float* bp = (const float*)d_in[2];
    const float* Wt = (const float*)d_in[3];
    const float* bt = (const float*)d_in[4];
    const float* Wb = (const float*)d_in[5];
    const float* bb = (const float*)d_in[6];
    float* out = (float*)d_out;
    (void)bt;

    static bool attr_done = false;
    if (!attr_done) {
        cudaFuncSetAttribute(k_gemm<0>, cudaFuncAttributeMaxDynamicSharedMemorySize, SM_TOTAL);
        cudaFuncSetAttribute(k_gemm<1>, cudaFuncAttributeMaxDynamicSharedMemorySize, SM_TOTAL);
        cudaFuncSetAttribute(k_gemm<2>, cudaFuncAttributeMaxDynamicSharedMemorySize, SM_TOTAL);
        cudaFuncSetAttribute(k_gemm<3>, cudaFuncAttributeMaxDynamicSharedMemorySize, SM_TOTAL);
        attr_done = true;
    }

    // launch order puts k_gemm<1> at position 6 (ncu captures launch #6)
    k_prep_w <<<dim3(16, 16, 3), 256>>>(Wp, Wt, Wb, bb);             // 1
    k_gemm<0><<<dim3(4, 4, 4), 256, SM_TOTAL>>>(nullptr, nullptr);   // 2: M split-K
    k_redM   <<<(Cd * Cd) / 256, 256>>>();                           // 3
    k_v      <<<16, 256>>>(Wt, bp);                                  // 4 (+ zero g_u)
    k_prep_x <<<dim3(Nd / 32, Cd / 32, Bd), 256>>>(X);               // 5 (+ u accum)
    k_gemm<1><<<dim3(8, 8, Bd), 256, SM_TOTAL>>>(nullptr, nullptr);  // 6: TT + beta
    k_gemm<2><<<dim3(8, 8, Bd), 256, SM_TOTAL>>>(nullptr, nullptr);  // 7: G -> ST + stats
    k_comb   <<<(Bd * Nd) / 256, 256>>>();                           // 8
    k_exps   <<<(Bd * Nd * Nd) / 1024, 256>>>();                     // 9
    k_gemm<3><<<dim3(8, 4, Bd), 256, SM_TOTAL>>>(X, out);            // 10: z -> out
}

// round 16
// speedup vs baseline: 1.3577x; 1.0108x over previous
#include <cuda_runtime.h>
#include <cuda_bf16.h>
#include <cstdint>

// ---------------------------------------------------------------------------
// Non-local attention block, B=8, C=512, N=1024 (H=W=32), fp32 in/out.
// R15: R14 + k_v re-parallelized (128 blocks, chunked q + atomicAdd) — the
//      atomic-free version was a 9us latency-bound serial loop (ncu R14).
//      g_v/g_u zeroing folded into k_prep_w.
// ---------------------------------------------------------------------------

namespace {
constexpr int Cd = 512, Nd = 1024, Bd = 8;
constexpr int ROWB   = 64;                 // 32 bf16 = 64B data, swizzled
constexpr int TILE_B = 128 * ROWB;         // 8192 B per operand-half tile
constexpr int BUF_B  = 4 * TILE_B;         // Ahi,Alo,Bhi,Blo = 32768 per stage
constexpr int STAGES = 3;
constexpr int SM_TOTAL = STAGES * BUF_B;   // 98304 -> 2 CTAs/SM
}

__device__ __forceinline__ uint32_t swz(uint32_t off) {
    return off ^ ((off >> 3) & 0x70);      // Swizzle<3,4,3> on 64B rows
}

// ---- device scratch --------------------------------------------------------
__device__ __nv_bfloat16 g_XT_hi[Bd * Nd * Cd];    // [b][n][c]
__device__ __nv_bfloat16 g_XT_lo[Bd * Nd * Cd];
__device__ __nv_bfloat16 g_WT_hi[2 * Cd * Cd];     // rows 0-511 WphiT, 512-1023 WthetaT
__device__ __nv_bfloat16 g_WT_lo[2 * Cd * Cd];
__device__ __nv_bfloat16 g_Wb_hi[Cd * Cd];         // Wbeta row-major [c][k]
__device__ __nv_bfloat16 g_Wb_lo[Cd * Cd];
__device__ float         g_bias_b[Cd];
__device__ float         g_v[Cd];                  // Wtheta^T bphi
__device__ float         g_u[Bd * Nd];             // v^T X_b
__device__ float         g_rmax[Bd * Nd];          // row max of S_eff
__device__ float         g_rinv[Bd * Nd];          // 1 / row sum exp
__device__ float         g_Mpart[4 * Cd * Cd];     // split-K partials for M
__device__ __nv_bfloat16 g_M_hi[Cd * Cd];          // [c][k]
__device__ __nv_bfloat16 g_M_lo[Cd * Cd];
__device__ __nv_bfloat16 g_TT_hi[Bd * Nd * Cd];    // [b][m][c]
__device__ __nv_bfloat16 g_TT_lo[Bd * Nd * Cd];
__device__ __nv_bfloat16 g_beta_hi[Bd * Cd * Nd];  // [b][c][n]
__device__ __nv_bfloat16 g_beta_lo[Bd * Cd * Nd];
__device__ float         g_S[Bd * Nd * Nd];        // ST: [b][m][n] (S transposed, no u)
__device__ float         g_pmax[Bd * Nd * 8];      // per-row per-coltile max
__device__ float         g_psum[Bd * Nd * 8];      // per-row per-coltile expsum
__device__ __nv_bfloat16 g_AT_hi[Bd * Nd * Nd];    // [b][m][n]
__device__ __nv_bfloat16 g_AT_lo[Bd * Nd * Nd];

// ---- helpers ---------------------------------------------------------------
__device__ __forceinline__ uint32_t smem_u32(const void* p) {
    uint32_t a;
    asm("{ .reg .u64 t; cvta.to.shared.u64 t, %1; cvt.u32.u64 %0, t; }"
        : "=r"(a) : "l"(p));
    return a;
}
__device__ __forceinline__ void cp16(uint32_t dst, const void* src) {
    asm volatile("cp.async.cg.shared.global [%0], [%1], 16;"
                 :: "r"(dst), "l"(__cvta_generic_to_global(src)) : "memory");
}
__device__ __forceinline__ void cp_commit() {
    asm volatile("cp.async.commit_group;" ::: "memory");
}
__device__ __forceinline__ void cp_wait1() {
    asm volatile("cp.async.wait_group 1;" ::: "memory");
}
__device__ __forceinline__ void ldm_x4(uint32_t (&r)[4], uint32_t addr) {
    asm volatile("ldmatrix.sync.aligned.m8n8.x4.shared.b16 {%0,%1,%2,%3}, [%4];"
        : "=r"(r[0]), "=r"(r[1]), "=r"(r[2]), "=r"(r[3]) : "r"(addr));
}
__device__ __forceinline__ void mma_bf16(float (&d)[4], const uint32_t (&a)[4],
                                         const uint32_t b0, const uint32_t b1) {
    asm volatile(
        "mma.sync.aligned.m16n8k16.row.col.f32.bf16.bf16.f32 "
        "{%0,%1,%2,%3},{%4,%5,%6,%7},{%8,%9},{%0,%1,%2,%3};"
        : "+f"(d[0]), "+f"(d[1]), "+f"(d[2]), "+f"(d[3])
        : "r"(a[0]), "r"(a[1]), "r"(a[2]), "r"(a[3]), "r"(b0), "r"(b1));
}
__device__ __forceinline__ void split_bf16(float v, __nv_bfloat16& h, __nv_bfloat16& l) {
    h = __float2bfloat16(v);
    l = __float2bfloat16(v - __bfloat162float(h));
}

// ---------------------------------------------------------------------------
// prep W (merged): z<2 -> transpose+split Wphi/Wtheta; z==2 -> split Wb + bias
// also zeroes g_v and g_u (needed by k_v / k_prep_x atomics later).
// ---------------------------------------------------------------------------
__global__ __launch_bounds__(256)
void k_prep_w(const float* __restrict__ Wp, const float* __restrict__ Wt,
              const float* __restrict__ Wb, const float* __restrict__ bb)
{
    if (blockIdx.z < 2) {
        __shared__ float t[32][33];
        const float* W = (blockIdx.z == 0) ? Wp : Wt;
        const int r0 = blockIdx.x * 32, q0 = blockIdx.y * 32;
        const int tx = threadIdx.x & 31, ty = threadIdx.x >> 5;
        #pragma unroll
        for (int r = 0; r < 4; r++)
            t[ty + 8 * r][tx] = W[(size_t)(q0 + ty + 8 * r) * Cd + r0 + tx];
        __syncthreads();
        #pragma unroll
        for (int r = 0; r < 4; r++) {
            float v = t[tx][ty + 8 * r];
            size_t o = ((size_t)blockIdx.z * Cd + r0 + ty + 8 * r) * Cd + q0 + tx;
            split_bf16(v, g_WT_hi[o], g_WT_lo[o]);
        }
    } else {
        const int flat = (blockIdx.y * 16 + blockIdx.x) * 256 + threadIdx.x;
        const int base = flat * 4;
        #pragma unroll
        for (int j = 0; j < 4; j++) {
            const int i = base + j;
            split_bf16(Wb[i], g_Wb_hi[i], g_Wb_lo[i]);
            if (i < Cd) g_bias_b[i] = bb[i];
        }
        if (flat < Cd) g_v[flat] = 0.f;
        if (flat < Bd * Nd) g_u[flat] = 0.f;
    }
}

// ---------------------------------------------------------------------------
// v[i] += sum_{q in chunk} Wt[q][i] * bphi[q]
// grid (16 i-blocks, 8 q-chunks), block 256 = (32 i, 8 q-subchunks of 8)
// ---------------------------------------------------------------------------
__global__ __launch_bounds__(256)
void k_v(const float* __restrict__ Wt, const float* __restrict__ bphi)
{
    __shared__ float part[8][32];
    const int i  = blockIdx.x * 32 + (threadIdx.x & 31);
    const int qs = threadIdx.x >> 5;
    const int q0 = blockIdx.y * 64 + qs * 8;
    float s = 0.f;
    #pragma unroll
    for (int r = 0; r < 8; r++) {
        const int q = q0 + r;
        s += Wt[(size_t)q * Cd + i] * bphi[q];
    }
    part[qs][threadIdx.x & 31] = s;
    __syncthreads();
    if (qs == 0) {
        float t = part[0][threadIdx.x];
        #pragma unroll
        for (int w = 1; w < 8; w++) t += part[w][threadIdx.x];
        atomicAdd(&g_v[i], t);
    }
}

// ---------------------------------------------------------------------------
// prep X: transpose + split XT[b][n][c] = X[b][c][n], and accumulate
// u[b][n] += sum_{c in tile} v[c] * X[b][c][n]
// ---------------------------------------------------------------------------
__global__ __launch_bounds__(256)
void k_prep_x(const float* __restrict__ X)
{
    __shared__ float t[32][33];
    const int b = blockIdx.z, n0 = blockIdx.x * 32, c0 = blockIdx.y * 32;
    const int tx = threadIdx.x & 31, ty = threadIdx.x >> 5;
    #pragma unroll
    for (int r = 0; r < 4; r++)
        t[ty + 8 * r][tx] = X[((size_t)b * Cd + c0 + ty + 8 * r) * Nd + n0 + tx];
    __syncthreads();

    float up = 0.f;
    #pragma unroll
    for (int r = 0; r < 4; r++) {
        const int cc = ty + 8 * r;
        up += g_v[c0 + cc] * t[cc][tx];  // X[c0+cc][n0+tx]
    }
    #pragma unroll
    for (int r = 0; r < 4; r++) {
        float v = t[tx][ty + 8 * r];
        size_t o = ((size_t)b * Nd + n0 + ty + 8 * r) * Cd + c0 + tx;
        split_bf16(v, g_XT_hi[o], g_XT_lo[o]);
    }
    __syncthreads();
    t[ty][tx] = up;
    __syncthreads();
    if (ty == 0) {
        float s = t[0][tx];
        #pragma unroll
        for (int w = 1; w < 8; w++) s += t[w][tx];
        atomicAdd(&g_u[b * Nd + n0 + tx], s);
    }
}

// ---------------------------------------------------------------------------
// reduce split-K partials of M and split to bf16 hi/lo
// ---------------------------------------------------------------------------
__global__ __launch_bounds__(256)
void k_redM()
{
    const int i = blockIdx.x * 256 + threadIdx.x;   // < Cd*Cd
    constexpr int CC = Cd * Cd;
    float s = (g_Mpart[i] + g_Mpart[i + CC]) + (g_Mpart[i + 2 * CC] + g_Mpart[i + 3 * CC]);
    split_bf16(s, g_M_hi[i], g_M_lo[i]);
}

// ---------------------------------------------------------------------------
// combine per-coltile softmax partials -> rmax, rinv (one thread per row)
// ---------------------------------------------------------------------------
__global__ __launch_bounds__(256)
void k_comb()
{
    const int r = blockIdx.x * 256 + threadIdx.x;   // < Bd*Nd
    float pm[8], psv[8];
    #pragma unroll
    for (int t = 0; t < 8; t++) {
        pm[t]  = g_pmax[(size_t)r * 8 + t];
        psv[t] = g_psum[(size_t)r * 8 + t];
    }
    float mb = pm[0];
    #pragma unroll
    for (int t = 1; t < 8; t++) mb = fmaxf(mb, pm[t]);
    float s = 0.f;
    #pragma unroll
    for (int t = 0; t < 8; t++) s += psv[t] * __expf(pm[t] - mb);
    g_rmax[r] = mb;
    g_rinv[r] = 1.0f / s;
}

// ---------------------------------------------------------------------------
// exps (streaming): AT[b][m][n] = split( exp(ST[b][m][n] + u[m] - rmax[n]) * rinv[n] )
// ---------------------------------------------------------------------------
__global__ __launch_bounds__(256)
void k_exps()
{
    const int flat = blockIdx.x * 256 + threadIdx.x;    // < Bd*Nd*256
    const int n4 = flat & 255;
    const int mg = flat >> 8;                           // global m row (b*Nd+m)
    const int b  = mg >> 10;
    const size_t o = ((size_t)mg) * Nd + n4 * 4;

    float4 st = *reinterpret_cast<const float4*>(g_S + o);
    const int nb = b * Nd + n4 * 4;
    float4 rm = *reinterpret_cast<const float4*>(g_rmax + nb);
    float4 ri = *reinterpret_cast<const float4*>(g_rinv + nb);
    const float um = g_u[mg];

    float e0 = __expf(st.x + um - rm.x) * ri.x;
    float e1 = __expf(st.y + um - rm.y) * ri.y;
    float e2 = __expf(st.z + um - rm.z) * ri.z;
    float e3 = __expf(st.w + um - rm.w) * ri.w;

    __nv_bfloat16 h0, l0, h1, l1, h2, l2, h3, l3;
    split_bf16(e0, h0, l0); split_bf16(e1, h1, l1);
    split_bf16(e2, h2, l2); split_bf16(e3, h3, l3);
    uint2 ph = make_uint2(
        (uint32_t)__bfloat16_as_ushort(h0) | ((uint32_t)__bfloat16_as_ushort(h1) << 16),
        (uint32_t)__bfloat16_as_ushort(h2) | ((uint32_t)__bfloat16_as_ushort(h3) << 16));
    uint2 pl = make_uint2(
        (uint32_t)__bfloat16_as_ushort(l0) | ((uint32_t)__bfloat16_as_ushort(l1) << 16),
        (uint32_t)__bfloat16_as_ushort(l2) | ((uint32_t)__bfloat16_as_ushort(l3) << 16));
    *reinterpret_cast<uint2*>(g_AT_hi + o) = ph;
    *reinterpret_cast<uint2*>(g_AT_lo + o) = pl;
}

// ---------------------------------------------------------------------------
// mma.sync GEMM: 256 threads, 8 warps (2x4), warp tile 64x32, CTA 128x128.
// BK=32, 3-stage cp.async pipeline (wait_group 1), swizzled 64B rows, 2 CTA/SM.
// MODE 0: M split-K  D[c][k] += WphiT . WthetaT (K chunk bz) -> g_Mpart fp32
// MODE 1: fused:  flat<32: TT = XT.M ; flat>=32: beta = Wb.XT (+bias)
// MODE 2: G  D[n][m] = XT . TT -> ST (transposed store) + partial softmax stats
// MODE 3: z  D[c][m] = beta . AT (+X)                   -> out fp32
// ---------------------------------------------------------------------------
template <int MODE>
__global__ __launch_bounds__(256, 2)
void k_gemm(const float* __restrict__ Xres, float* __restrict__ Out)
{
    extern __shared__ __align__(1024) char smem[];
    const uint32_t sbase = smem_u32(smem);
    const int tid = threadIdx.x;
    const int lane = tid & 31, wid = tid >> 5;
    const int wr = wid >> 2, wc = wid & 3;          // 2x4 warp grid
    const int bz = blockIdx.z;

    int m0, n0;
    bool isTT = true;
    if (MODE == 1) {
        const int flat = blockIdx.y * 8 + blockIdx.x;   // 0..63
        isTT = flat < 32;
        if (isTT) { m0 = (flat >> 2) * 128; n0 = (flat & 3) * 128; }
        else      { const int f2 = flat - 32; m0 = (f2 >> 3) * 128; n0 = (f2 & 7) * 128; }
    } else {
        m0 = blockIdx.y * 128; n0 = blockIdx.x * 128;
    }

    const __nv_bfloat16 *Ah, *Al, *Bh, *Bl;
    int ldA, ldB;
    constexpr int K = (MODE == 3) ? Nd : ((MODE == 0) ? 128 : Cd);
    const int kbase = (MODE == 0) ? bz * 128 : 0;
    if (MODE == 0) {
        Ah = g_WT_hi;               Al = g_WT_lo;
        Bh = g_WT_hi + Cd * Cd;     Bl = g_WT_lo + Cd * Cd;
        ldA = Cd; ldB = Cd;
    } else if (MODE == 1) {
        if (isTT) {
            Ah = g_XT_hi + (size_t)bz * Nd * Cd;  Al = g_XT_lo + (size_t)bz * Nd * Cd;
            Bh = g_M_hi;                          Bl = g_M_lo;
        } else {
            Ah = g_Wb_hi;                         Al = g_Wb_lo;
            Bh = g_XT_hi + (size_t)bz * Nd * Cd;  Bl = g_XT_lo + (size_t)bz * Nd * Cd;
        }
        ldA = Cd; ldB = Cd;
    } else if (MODE == 2) {
        Ah = g_XT_hi + (size_t)bz * Nd * Cd;  Al = g_XT_lo + (size_t)bz * Nd * Cd;
        Bh = g_TT_hi + (size_t)bz * Nd * Cd;  Bl = g_TT_lo + (size_t)bz * Nd * Cd;
        ldA = Cd; ldB = Cd;
    } else {
        Ah = g_beta_hi + (size_t)bz * Cd * Nd;  Al = g_beta_lo + (size_t)bz * Cd * Nd;
        Bh = g_AT_hi + (size_t)bz * Nd * Nd;    Bl = g_AT_lo + (size_t)bz * Nd * Nd;
        ldA = Nd; ldB = Nd;
    }

    // loader role: quarter oh -> one operand-half; 8 cp.async per k-tile
    const int oh = tid >> 6, lt = tid & 63;
    const __nv_bfloat16* src;
    int row0, ld;
    if      (oh == 0) { src = Ah; row0 = m0; ld = ldA; }
    else if (oh == 1) { src = Al; row0 = m0; ld = ldA; }
    else if (oh == 2) { src = Bh; row0 = n0; ld = ldB; }
    else              { src = Bl; row0 = n0; ld = ldB; }

    auto cp_tile = [&](int buf, int k0) {
        const uint32_t sb = sbase + buf * BUF_B + oh * TILE_B;
        #pragma unroll
        for (int i = 0; i < 8; i++) {
            const int j = i * 64 + lt;
            const int row = j >> 2, c = j & 3;
            cp16(sb + swz(row * ROWB + c * 16),
                 src + (size_t)(row0 + row) * ld + k0 + c * 8);
        }
        cp_commit();
    };

    float acc[4][4][4];
    #pragma unroll
    for (int i = 0; i < 4; i++)
        #pragma unroll
        for (int j = 0; j < 4; j++)
            #pragma unroll
            for (int q = 0; q < 4; q++) acc[i][j][q] = 0.f;

    // ldmatrix lane address components
    const int a_r = lane & 15, a_c = lane >> 4;
    const int b_r = (lane & 7) + ((lane & 16) >> 1);
    const int b_c = (lane >> 3) & 1;

    // prologue: 2 stages in flight
    cp_tile(0, kbase);
    cp_tile(1, kbase + 32);

    constexpr int NT = K / 32;
    int buf = 0;
    for (int t = 0; t < NT; t++) {
        cp_wait1();                 // tile t complete (<=1 group pending)
        __syncthreads();
        if (t + 2 < NT) cp_tile((buf + 2) % 3, kbase + (t + 2) * 32);
        else            cp_commit();   // keep group-count invariant

        const uint32_t sAh = sbase + buf * BUF_B;
        const uint32_t sAl = sAh + TILE_B;
        const uint32_t sBh = sAh + 2 * TILE_B;
        const uint32_t sBl = sAh + 3 * TILE_B;

        #pragma unroll
        for (int ks = 0; ks < 2; ks++) {
            uint32_t bhi[4][2], blo[4][2];
            #pragma unroll
            for (int p = 0; p < 2; p++) {
                const uint32_t off = swz((uint32_t)(wc * 32 + p * 16 + b_r) * ROWB
                                         + (uint32_t)(ks * 2 + b_c) * 16);
                uint32_t th[4], tl[4];
                ldm_x4(th, sBh + off);
                ldm_x4(tl, sBl + off);
                bhi[2 * p][0] = th[0]; bhi[2 * p][1] = th[1];
                bhi[2 * p + 1][0] = th[2]; bhi[2 * p + 1][1] = th[3];
                blo[2 * p][0] = tl[0]; blo[2 * p][1] = tl[1];
                blo[2 * p + 1][0] = tl[2]; blo[2 * p + 1][1] = tl[3];
            }
            #pragma unroll
            for (int mt = 0; mt < 4; mt++) {
                uint32_t ahi[4], alo[4];
                const uint32_t off = swz((uint32_t)(wr * 64 + mt * 16 + a_r) * ROWB
                                         + (uint32_t)(ks * 2 + a_c) * 16);
                ldm_x4(ahi, sAh + off);
                ldm_x4(alo, sAl + off);
                #pragma unroll
                for (int nt = 0; nt < 4; nt++) {
                    mma_bf16(acc[mt][nt], ahi, bhi[nt][0], bhi[nt][1]);
                    mma_bf16(acc[mt][nt], ahi, blo[nt][0], blo[nt][1]);
                    mma_bf16(acc[mt][nt], alo, bhi[nt][0], bhi[nt][1]);
                }
            }
        }
        buf = (buf + 1) % 3;
    }

    // epilogue: fragment lane -> (row = lane>>2 [+8], cols (lane&3)*2, +1)
    #pragma unroll
    for (int mt = 0; mt < 4; mt++)
        #pragma unroll
        for (int nt = 0; nt < 4; nt++) {
            const int row = m0 + wr * 64 + mt * 16 + (lane >> 2);
            const int col = n0 + wc * 32 + nt * 8 + (lane & 3) * 2;
            const float* d = acc[mt][nt];

            if (MODE == 0) {
                float* Mp = g_Mpart + (size_t)bz * Cd * Cd;
                const size_t o0 = (size_t)row * Cd + col;
                *reinterpret_cast<float2*>(Mp + o0) = make_float2(d[0], d[1]);
                *reinterpret_cast<float2*>(Mp + o0 + 8 * Cd) = make_float2(d[2], d[3]);
            } else if (MODE == 1) {
                float q0 = d[0], q1 = d[1], q2 = d[2], q3 = d[3];
                __nv_bfloat16 *dh, *dl;
                size_t o0;
                int ldo;
                if (isTT) {
                    ldo = Cd; o0 = ((size_t)bz * Nd + row) * ldo + col;
                    dh = g_TT_hi; dl = g_TT_lo;
                } else {
                    q0 += g_bias_b[row];     q1 += g_bias_b[row];
                    q2 += g_bias_b[row + 8]; q3 += g_bias_b[row + 8];
                    ldo = Nd; o0 = ((size_t)bz * Cd + row) * ldo + col;
                    dh = g_beta_hi; dl = g_beta_lo;
                }
                __nv_bfloat16 h0, l0, h1, l1, h2, l2, h3, l3;
                split_bf16(q0, h0, l0); split_bf16(q1, h1, l1);
                split_bf16(q2, h2, l2); split_bf16(q3, h3, l3);
                const size_t o1 = o0 + 8 * (size_t)ldo;
                *reinterpret_cast<uint32_t*>(dh + o0) =
                    (uint32_t)__bfloat16_as_ushort(h0) | ((uint32_t)__bfloat16_as_ushort(h1) << 16);
                *reinterpret_cast<uint32_t*>(dl + o0) =
                    (uint32_t)__bfloat16_as_ushort(l0) | ((uint32_t)__bfloat16_as_ushort(l1) << 16);
                *reinterpret_cast<uint32_t*>(dh + o1) =
                    (uint32_t)__bfloat16_as_ushort(h2) | ((uint32_t)__bfloat16_as_ushort(h3) << 16);
                *reinterpret_cast<uint32_t*>(dl + o1) =
                    (uint32_t)__bfloat16_as_ushort(l2) | ((uint32_t)__bfloat16_as_ushort(l3) << 16);
            } else if (MODE == 2) {
                // transposed store: ST[b][m=col][n=row]
                const size_t o = ((size_t)bz * Nd + col) * Nd + row;
                g_S[o]          = d[0];
                g_S[o + Nd]     = d[1];
                g_S[o + 8]      = d[2];
                g_S[o + Nd + 8] = d[3];
            } else {
                const size_t o0 = ((size_t)bz * Cd + row) * Nd + col;
                const size_t o1 = o0 + 8 * Nd;
                float2 x0 = *reinterpret_cast<const float2*>(Xres + o0);
                float2 x1 = *reinterpret_cast<const float2*>(Xres + o1);
                *reinterpret_cast<float2*>(Out + o0) = make_float2(d[0] + x0.x, d[1] + x0.y);
                *reinterpret_cast<float2*>(Out + o1) = make_float2(d[2] + x1.x, d[3] + x1.y);
            }
        }

    // MODE 2: fused partial softmax stats over this CTA's 128-col tile.
    if (MODE == 2) {
        __syncthreads();                              // pipeline smem now free
        float* pm = reinterpret_cast<float*>(smem);   // [4][128]
        float* ps = pm + 512;                          // [4][128]

        #pragma unroll
        for (int mt = 0; mt < 4; mt++) {
            float vs[4][4];
            float mx0 = -1e30f, mx1 = -1e30f;
            #pragma unroll
            for (int nt = 0; nt < 4; nt++) {
                const int col = n0 + wc * 32 + nt * 8 + (lane & 3) * 2;
                const float u0 = g_u[bz * Nd + col];
                const float u1 = g_u[bz * Nd + col + 1];
                const float* d = acc[mt][nt];
                vs[nt][0] = d[0] + u0; vs[nt][1] = d[1] + u1;
                vs[nt][2] = d[2] + u0; vs[nt][3] = d[3] + u1;
                mx0 = fmaxf(mx0, fmaxf(vs[nt][0], vs[nt][1]));
                mx1 = fmaxf(mx1, fmaxf(vs[nt][2], vs[nt][3]));
            }
            mx0 = fmaxf(mx0, __shfl_xor_sync(0xffffffffu, mx0, 1));
            mx0 = fmaxf(mx0, __shfl_xor_sync(0xffffffffu, mx0, 2));
            mx1 = fmaxf(mx1, __shfl_xor_sync(0xffffffffu, mx1, 1));
            mx1 = fmaxf(mx1, __shfl_xor_sync(0xffffffffu, mx1, 2));
            float s0 = 0.f, s1 = 0.f;
            #pragma unroll
            for (int nt = 0; nt < 4; nt++) {
                s0 += __expf(vs[nt][0] - mx0) + __expf(vs[nt][1] - mx0);
                s1 += __expf(vs[nt][2] - mx1) + __expf(vs[nt][3] - mx1);
            }
            s0 += __shfl_xor_sync(0xffffffffu, s0, 1);
            s0 += __shfl_xor_sync(0xffffffffu, s0, 2);
            s1 += __shfl_xor_sync(0xffffffffu, s1, 1);
            s1 += __shfl_xor_sync(0xffffffffu, s1, 2);
            if ((lane & 3) == 0) {
                const int rl = wr * 64 + mt * 16 + (lane >> 2);
                pm[wc * 128 + rl]     = mx0;  ps[wc * 128 + rl]     = s0;
                pm[wc * 128 + rl + 8] = mx1;  ps[wc * 128 + rl + 8] = s1;
            }
        }
        __syncthreads();
        if (tid < 128) {
            float mb = pm[tid];
            #pragma unroll
            for (int w = 1; w < 4; w++) mb = fmaxf(mb, pm[w * 128 + tid]);
            float sb = 0.f;
            #pragma unroll
            for (int w = 0; w < 4; w++)
                sb += ps[w * 128 + tid] * __expf(pm[w * 128 + tid] - mb);
            const size_t o = ((size_t)bz * Nd + m0 + tid) * 8 + (n0 >> 7);
            g_pmax[o] = mb;
            g_psum[o] = sb;
        }
    }
}

// ---------------------------------------------------------------------------
extern "C" void kernel_launch(void* const* d_in, const int* in_sizes, int n_in,
                              void* d_out, int out_size)
{
    (void)in_sizes; (void)n_in; (void)out_size;
    const float* X  = (const float*)d_in[0];
    const float* Wp = (const float*)d_in[1];
    const float* bp = (const float*)d_in[2];
    const float* Wt = (const float*)d_in[3];
    const float* bt = (const float*)d_in[4];
    const float* Wb = (const float*)d_in[5];
    const float* bb = (const float*)d_in[6];
    float* out = (float*)d_out;
    (void)bt;

    static bool attr_done = false;
    if (!attr_done) {
        cudaFuncSetAttribute(k_gemm<0>, cudaFuncAttributeMaxDynamicSharedMemorySize, SM_TOTAL);
        cudaFuncSetAttribute(k_gemm<1>, cudaFuncAttributeMaxDynamicSharedMemorySize, SM_TOTAL);
        cudaFuncSetAttribute(k_gemm<2>, cudaFuncAttributeMaxDynamicSharedMemorySize, SM_TOTAL);
        cudaFuncSetAttribute(k_gemm<3>, cudaFuncAttributeMaxDynamicSharedMemorySize, SM_TOTAL);
        attr_done = true;
    }

    k_prep_w <<<dim3(16, 16, 3), 256>>>(Wp, Wt, Wb, bb);             // 1 (+ zero v,u)
    k_gemm<0><<<dim3(4, 4, 4), 256, SM_TOTAL>>>(nullptr, nullptr);   // 2: M split-K
    k_redM   <<<(Cd * Cd) / 256, 256>>>();                           // 3
    k_v      <<<dim3(16, 8), 256>>>(Wt, bp);                         // 4
    k_prep_x <<<dim3(Nd / 32, Cd / 32, Bd), 256>>>(X);               // 5 (+ u accum)
    k_gemm<1><<<dim3(8, 8, Bd), 256, SM_TOTAL>>>(nullptr, nullptr);  // 6: TT + beta
    k_gemm<2><<<dim3(8, 8, Bd), 256, SM_TOTAL>>>(nullptr, nullptr);  // 7: G -> ST + stats
    k_comb   <<<(Bd * Nd) / 256, 256>>>();                           // 8
    k_exps   <<<(Bd * Nd * Nd) / 1024, 256>>>();                     // 9
    k_gemm<3><<<dim3(8, 4, Bd), 256, SM_TOTAL>>>(X, out);            // 10: z -> out
}